// round 1
// baseline (speedup 1.0000x reference)
#include <cuda_runtime.h>

// Problem constants
constexpr int B    = 2;
constexpr int SEQ  = 2048;
constexpr int C    = 1024;
constexpr int H    = 16;
constexpr int D    = 64;          // C / H
constexpr int BH   = B * H;       // 32
constexpr int MTOT = B * SEQ;     // 4096
constexpr int KDIM = C;           // GEMM reduction dim

// Scratch (allocation-free rule: __device__ globals)
__device__ float g_q[BH * SEQ * D];   // [B,H,N,D], pre-scaled by 1/sqrt(D)
__device__ float g_k[BH * SEQ * D];   // [B,H,N,D]
__device__ float g_v[BH * SEQ * D];   // [B,H,N,D]
__device__ float g_o[MTOT * C];       // [B,N,C] attention output

// ---------------------------------------------------------------------------
// GEMM (NT): Y[m,j] = sum_k A[m,k] * W[j,k]   (A: [M,K] rm, W: [NN,K] rm)
// MODE 0: NN=3072, scatter epilogue into g_q (scaled), g_k, g_v
// MODE 1: NN=1024, A = g_o, epilogue adds bias, writes to out
// Tile: 128x128x16, 256 threads, 8x8 per thread, register prefetch.
// ---------------------------------------------------------------------------
template <int MODE, int NN>
__global__ __launch_bounds__(256)
void gemm_nt(const float* __restrict__ A, const float* __restrict__ W,
             const float* __restrict__ bias, float* __restrict__ out)
{
    constexpr int BM = 128, BN = 128, BK = 16;
    __shared__ float As[BK][BM];   // transposed: [k][m]
    __shared__ float Bs[BK][BN];   // transposed: [k][n]

    const int tid = threadIdx.x;
    const int tx = tid & 15;       // 0..15 -> n direction
    const int ty = tid >> 4;       // 0..15 -> m direction
    const int m0 = blockIdx.y * BM;
    const int n0 = blockIdx.x * BN;

    const float* Abase = (MODE == 1) ? &g_o[0] : A;

    // loader mapping: each thread loads 2 float4 per matrix per k-tile
    const int lrow = tid >> 2;            // 0..63
    const int lcol = (tid & 3) << 2;      // 0,4,8,12

    const float* aptr = Abase + (long)(m0 + lrow) * KDIM + lcol;
    const float* wptr = W     + (long)(n0 + lrow) * KDIM + lcol;

    float acc[8][8];
#pragma unroll
    for (int i = 0; i < 8; i++)
#pragma unroll
        for (int j = 0; j < 8; j++) acc[i][j] = 0.f;

    float4 pa0, pa1, pb0, pb1;

    // initial load (k0 = 0)
    pa0 = *(const float4*)(aptr);
    pa1 = *(const float4*)(aptr + 64 * KDIM);
    pb0 = *(const float4*)(wptr);
    pb1 = *(const float4*)(wptr + 64 * KDIM);

    // store transposed into smem
    As[lcol + 0][lrow] = pa0.x; As[lcol + 1][lrow] = pa0.y;
    As[lcol + 2][lrow] = pa0.z; As[lcol + 3][lrow] = pa0.w;
    As[lcol + 0][lrow + 64] = pa1.x; As[lcol + 1][lrow + 64] = pa1.y;
    As[lcol + 2][lrow + 64] = pa1.z; As[lcol + 3][lrow + 64] = pa1.w;
    Bs[lcol + 0][lrow] = pb0.x; Bs[lcol + 1][lrow] = pb0.y;
    Bs[lcol + 2][lrow] = pb0.z; Bs[lcol + 3][lrow] = pb0.w;
    Bs[lcol + 0][lrow + 64] = pb1.x; Bs[lcol + 1][lrow + 64] = pb1.y;
    Bs[lcol + 2][lrow + 64] = pb1.z; Bs[lcol + 3][lrow + 64] = pb1.w;
    __syncthreads();

    constexpr int KT = KDIM / BK;   // 64
    for (int kt = 0; kt < KT; ++kt) {
        if (kt + 1 < KT) {
            const int k0 = (kt + 1) * BK;
            pa0 = *(const float4*)(aptr + k0);
            pa1 = *(const float4*)(aptr + 64 * KDIM + k0);
            pb0 = *(const float4*)(wptr + k0);
            pb1 = *(const float4*)(wptr + 64 * KDIM + k0);
        }

#pragma unroll
        for (int kk = 0; kk < BK; ++kk) {
            float4 a0 = *(const float4*)&As[kk][ty * 8];
            float4 a1 = *(const float4*)&As[kk][ty * 8 + 4];
            float4 b0 = *(const float4*)&Bs[kk][tx * 8];
            float4 b1 = *(const float4*)&Bs[kk][tx * 8 + 4];
            float av[8] = {a0.x, a0.y, a0.z, a0.w, a1.x, a1.y, a1.z, a1.w};
            float bv[8] = {b0.x, b0.y, b0.z, b0.w, b1.x, b1.y, b1.z, b1.w};
#pragma unroll
            for (int i = 0; i < 8; i++)
#pragma unroll
                for (int j = 0; j < 8; j++)
                    acc[i][j] += av[i] * bv[j];
        }
        __syncthreads();
        if (kt + 1 < KT) {
            As[lcol + 0][lrow] = pa0.x; As[lcol + 1][lrow] = pa0.y;
            As[lcol + 2][lrow] = pa0.z; As[lcol + 3][lrow] = pa0.w;
            As[lcol + 0][lrow + 64] = pa1.x; As[lcol + 1][lrow + 64] = pa1.y;
            As[lcol + 2][lrow + 64] = pa1.z; As[lcol + 3][lrow + 64] = pa1.w;
            Bs[lcol + 0][lrow] = pb0.x; Bs[lcol + 1][lrow] = pb0.y;
            Bs[lcol + 2][lrow] = pb0.z; Bs[lcol + 3][lrow] = pb0.w;
            Bs[lcol + 0][lrow + 64] = pb1.x; Bs[lcol + 1][lrow + 64] = pb1.y;
            Bs[lcol + 2][lrow + 64] = pb1.z; Bs[lcol + 3][lrow + 64] = pb1.w;
            __syncthreads();
        }
    }

    // -------- epilogue --------
    if (MODE == 0) {
        // scatter into Q (scaled), K, V in [B,H,N,D]
#pragma unroll
        for (int i = 0; i < 8; i++) {
            const int m = m0 + ty * 8 + i;
            const int b = m >> 11;          // /2048
            const int n = m & 2047;
#pragma unroll
            for (int j = 0; j < 8; j++) {
                const int col = n0 + tx * 8 + j;
                const int which = col >> 10;      // 0=q 1=k 2=v
                const int r = col & 1023;
                const int h = r >> 6;
                const int d = r & 63;
                const long idx = ((long)((b * H + h) * SEQ + n)) * D + d;
                const float v = acc[i][j];
                if (which == 0)       g_q[idx] = v * 0.125f;   // 1/sqrt(64)
                else if (which == 1)  g_k[idx] = v;
                else                  g_v[idx] = v;
            }
        }
    } else {
        // bias + write to out [MTOT, NN]
#pragma unroll
        for (int i = 0; i < 8; i++) {
            const int m = m0 + ty * 8 + i;
            float* op = out + (long)m * NN + n0 + tx * 8;
#pragma unroll
            for (int j = 0; j < 8; j++)
                op[j] = acc[i][j] + bias[n0 + tx * 8 + j];
        }
    }
}

// ---------------------------------------------------------------------------
// Flash attention: 1 thread = 1 query row. 128 rows / CTA.
// K/V processed in 32-row tiles via shared memory (broadcast LDS.128 reads).
// Q is pre-scaled. Online softmax in fp32.
// grid: (SEQ/128, BH)
// ---------------------------------------------------------------------------
__global__ __launch_bounds__(128)
void attn_kernel()
{
    constexpr int BKV = 32;
    __shared__ float Ks[BKV][D];
    __shared__ float Vs[BKV][D];

    const int tid = threadIdx.x;
    const int bh  = blockIdx.y;
    const int row = blockIdx.x * 128 + tid;

    // load q row into registers
    float q[D];
    {
        const float4* qp = (const float4*)(g_q + ((long)bh * SEQ + row) * D);
#pragma unroll
        for (int i = 0; i < 16; i++) {
            float4 v = qp[i];
            q[4 * i + 0] = v.x; q[4 * i + 1] = v.y;
            q[4 * i + 2] = v.z; q[4 * i + 3] = v.w;
        }
    }

    float o[D];
#pragma unroll
    for (int d = 0; d < D; d++) o[d] = 0.f;
    float mx = -1e30f, l = 0.f;

    const float4* kbase = (const float4*)(g_k + (long)bh * SEQ * D);
    const float4* vbase = (const float4*)(g_v + (long)bh * SEQ * D);
    float4* Kd = (float4*)&Ks[0][0];
    float4* Vd = (float4*)&Vs[0][0];
    const float4* Ks4 = (const float4*)&Ks[0][0];
    const float4* Vs4 = (const float4*)&Vs[0][0];

    for (int kb = 0; kb < SEQ / BKV; ++kb) {
        // load K/V tile: 512 float4 each, 128 threads -> 4 each (coalesced)
        const float4* ks = kbase + kb * (BKV * D / 4);
        const float4* vs = vbase + kb * (BKV * D / 4);
#pragma unroll
        for (int i = 0; i < 4; i++) {
            Kd[i * 128 + tid] = ks[i * 128 + tid];
            Vd[i * 128 + tid] = vs[i * 128 + tid];
        }
        __syncthreads();

        // scores: s[j] = q . K_j   (broadcast LDS.128, 4 FMA per LDS)
        float s[BKV];
#pragma unroll
        for (int j = 0; j < BKV; j++) {
            float a0 = 0.f, a1 = 0.f, a2 = 0.f, a3 = 0.f;
#pragma unroll
            for (int d4 = 0; d4 < 16; d4++) {
                float4 kv = Ks4[j * 16 + d4];
                a0 += q[4 * d4 + 0] * kv.x;
                a1 += q[4 * d4 + 1] * kv.y;
                a2 += q[4 * d4 + 2] * kv.z;
                a3 += q[4 * d4 + 3] * kv.w;
            }
            s[j] = (a0 + a1) + (a2 + a3);
        }

        // online softmax
        float bm = mx;
#pragma unroll
        for (int j = 0; j < BKV; j++) bm = fmaxf(bm, s[j]);
        const float alpha = __expf(mx - bm);
        mx = bm;
        float ps = 0.f;
#pragma unroll
        for (int j = 0; j < BKV; j++) { s[j] = __expf(s[j] - bm); ps += s[j]; }
        l = l * alpha + ps;

#pragma unroll
        for (int d = 0; d < D; d++) o[d] *= alpha;
#pragma unroll
        for (int j = 0; j < BKV; j++) {
            const float p = s[j];
#pragma unroll
            for (int d4 = 0; d4 < 16; d4++) {
                float4 vv = Vs4[j * 16 + d4];
                o[4 * d4 + 0] += p * vv.x;
                o[4 * d4 + 1] += p * vv.y;
                o[4 * d4 + 2] += p * vv.z;
                o[4 * d4 + 3] += p * vv.w;
            }
        }
        __syncthreads();
    }

    // normalize + write to g_o as [B, N, C] (b, row, h*64 + d)
    const float inv = 1.f / l;
    const int b = bh >> 4;
    const int h = bh & 15;
    float4* op = (float4*)(g_o + ((long)(b * SEQ + row)) * C + h * D);
#pragma unroll
    for (int i = 0; i < 16; i++) {
        float4 v;
        v.x = o[4 * i + 0] * inv;
        v.y = o[4 * i + 1] * inv;
        v.z = o[4 * i + 2] * inv;
        v.w = o[4 * i + 3] * inv;
        op[i] = v;
    }
}

// ---------------------------------------------------------------------------
extern "C" void kernel_launch(void* const* d_in, const int* in_sizes, int n_in,
                              void* d_out, int out_size)
{
    const float* x      = (const float*)d_in[0];   // [B,N,C]
    const float* w_qkv  = (const float*)d_in[1];   // [3C, C]
    const float* w_proj = (const float*)d_in[2];   // [C, C]
    const float* b_proj = (const float*)d_in[3];   // [C]
    float* out = (float*)d_out;                    // [B,N,C]

    // 1) QKV projection -> g_q (scaled), g_k, g_v
    gemm_nt<0, 3 * C><<<dim3(3 * C / 128, MTOT / 128), 256>>>(x, w_qkv, nullptr, nullptr);

    // 2) attention -> g_o [B,N,C]
    attn_kernel<<<dim3(SEQ / 128, BH), 128>>>();

    // 3) output projection + bias -> out
    gemm_nt<1, C><<<dim3(C / 128, MTOT / 128), 256>>>(nullptr, w_proj, b_proj, out);
}

// round 2
// speedup vs baseline: 3.2860x; 3.2860x over previous
#include <cuda_runtime.h>

// Problem constants
constexpr int B    = 2;
constexpr int SEQ  = 2048;
constexpr int C    = 1024;
constexpr int H    = 16;
constexpr int D    = 64;
constexpr int BH   = B * H;       // 32
constexpr int MTOT = B * SEQ;     // 4096
constexpr int KDIM = C;

// Scratch (allocation-free rule: __device__ globals)
__device__ float g_q[BH * SEQ * D];   // [B,H,N,D], pre-scaled by 1/sqrt(D), tf32-rounded
__device__ float g_k[BH * SEQ * D];   // tf32-rounded
__device__ float g_v[BH * SEQ * D];   // tf32-rounded
__device__ float g_o[MTOT * C];       // [B,N,C] attention output (fp32)

__device__ __forceinline__ float tf32r(float x) {
    asm("cvt.rna.tf32.f32 %0, %0;" : "+f"(x));
    return x;
}

__device__ __forceinline__ void mma8(float* d, const unsigned* a, const unsigned* b) {
    asm volatile(
        "mma.sync.aligned.m16n8k8.row.col.f32.tf32.tf32.f32 "
        "{%0,%1,%2,%3}, {%4,%5,%6,%7}, {%8,%9}, {%0,%1,%2,%3};\n"
        : "+f"(d[0]), "+f"(d[1]), "+f"(d[2]), "+f"(d[3])
        : "r"(a[0]), "r"(a[1]), "r"(a[2]), "r"(a[3]), "r"(b[0]), "r"(b[1]));
}

// ---------------------------------------------------------------------------
// tf32 tensor-core GEMM (NT): Y[m,j] = sum_k A[m,k] * W[j,k]
// Tile 128x128x16, 256 threads (8 warps, 2x4), warp tile 64x32.
// smem stride 20 words -> conflict-free fragment loads.
// MODE 0: scatter epilogue -> g_q (scaled+rounded), g_k, g_v (rounded)
// MODE 1: A = g_o, bias add, write out
// ---------------------------------------------------------------------------
template <int MODE, int NN>
__global__ __launch_bounds__(256)
void gemm_mma(const float* __restrict__ A, const float* __restrict__ W,
              const float* __restrict__ bias, float* __restrict__ out)
{
    constexpr int BM = 128, BN = 128, BK = 16, SA = BK + 4;  // stride 20
    __shared__ float As[BM * SA];
    __shared__ float Bs[BN * SA];

    const int tid  = threadIdx.x;
    const int warp = tid >> 5, lane = tid & 31;
    const int g = lane >> 2, t = lane & 3;
    const int wm = (warp >> 2) * 64;      // 0 or 64
    const int wn = (warp & 3) * 32;       // 0,32,64,96
    const int m0 = blockIdx.y * BM;
    const int n0 = blockIdx.x * BN;

    const float* Abase = (MODE == 1) ? &g_o[0] : A;

    const int lrow = tid >> 2;            // 0..63
    const int lcol = (tid & 3) << 2;      // 0,4,8,12
    const float* aptr = Abase + (size_t)(m0 + lrow) * KDIM + lcol;
    const float* wptr = W     + (size_t)(n0 + lrow) * KDIM + lcol;

    float acc[4][4][4];
#pragma unroll
    for (int mt = 0; mt < 4; mt++)
#pragma unroll
        for (int nt = 0; nt < 4; nt++)
#pragma unroll
            for (int j = 0; j < 4; j++) acc[mt][nt][j] = 0.f;

    auto stash = [&](float* base, int row, float4 v) {
        float* p = base + row * SA + lcol;
        p[0] = tf32r(v.x); p[1] = tf32r(v.y); p[2] = tf32r(v.z); p[3] = tf32r(v.w);
    };

    float4 pa0, pa1, pb0, pb1;
    pa0 = *(const float4*)(aptr);
    pa1 = *(const float4*)(aptr + 64 * KDIM);
    pb0 = *(const float4*)(wptr);
    pb1 = *(const float4*)(wptr + 64 * KDIM);
    stash(As, lrow, pa0); stash(As, lrow + 64, pa1);
    stash(Bs, lrow, pb0); stash(Bs, lrow + 64, pb1);
    __syncthreads();

    constexpr int KT = KDIM / BK;  // 64
    for (int kt = 0; kt < KT; ++kt) {
        if (kt + 1 < KT) {
            const int k0 = (kt + 1) * BK;
            pa0 = *(const float4*)(aptr + k0);
            pa1 = *(const float4*)(aptr + 64 * KDIM + k0);
            pb0 = *(const float4*)(wptr + k0);
            pb1 = *(const float4*)(wptr + 64 * KDIM + k0);
        }

#pragma unroll
        for (int ks = 0; ks < 2; ks++) {
            const int k0 = ks * 8;
            unsigned af[4][4], bf[4][2];
#pragma unroll
            for (int mt = 0; mt < 4; mt++) {
                const int r0 = (wm + mt * 16 + g) * SA + k0 + t;
                const int r1 = (wm + mt * 16 + g + 8) * SA + k0 + t;
                af[mt][0] = __float_as_uint(As[r0]);
                af[mt][1] = __float_as_uint(As[r1]);
                af[mt][2] = __float_as_uint(As[r0 + 4]);
                af[mt][3] = __float_as_uint(As[r1 + 4]);
            }
#pragma unroll
            for (int nt = 0; nt < 4; nt++) {
                const int r = (wn + nt * 8 + g) * SA + k0 + t;
                bf[nt][0] = __float_as_uint(Bs[r]);
                bf[nt][1] = __float_as_uint(Bs[r + 4]);
            }
#pragma unroll
            for (int mt = 0; mt < 4; mt++)
#pragma unroll
                for (int nt = 0; nt < 4; nt++)
                    mma8(acc[mt][nt], af[mt], bf[nt]);
        }
        __syncthreads();
        if (kt + 1 < KT) {
            stash(As, lrow, pa0); stash(As, lrow + 64, pa1);
            stash(Bs, lrow, pb0); stash(Bs, lrow + 64, pb1);
            __syncthreads();
        }
    }

    // -------- epilogue --------
    if (MODE == 0) {
#pragma unroll
        for (int mt = 0; mt < 4; mt++) {
#pragma unroll
            for (int rr = 0; rr < 2; rr++) {
                const int m = m0 + wm + mt * 16 + g + rr * 8;
                const int b = m >> 11;
                const int n = m & 2047;
#pragma unroll
                for (int nt = 0; nt < 4; nt++) {
#pragma unroll
                    for (int j = 0; j < 2; j++) {
                        const int col = n0 + wn + nt * 8 + 2 * t + j;
                        const float v = acc[mt][nt][rr * 2 + j];
                        const int which = col >> 10;
                        const int r = col & 1023;
                        const int h = r >> 6;
                        const int d = r & 63;
                        const size_t idx = ((size_t)((b * H + h) * SEQ + n)) * D + d;
                        if (which == 0)      g_q[idx] = tf32r(v * 0.125f);
                        else if (which == 1) g_k[idx] = tf32r(v);
                        else                 g_v[idx] = tf32r(v);
                    }
                }
            }
        }
    } else {
#pragma unroll
        for (int mt = 0; mt < 4; mt++) {
#pragma unroll
            for (int rr = 0; rr < 2; rr++) {
                const int m = m0 + wm + mt * 16 + g + rr * 8;
#pragma unroll
                for (int nt = 0; nt < 4; nt++) {
                    const int col = n0 + wn + nt * 8 + 2 * t;
                    float2 v;
                    v.x = acc[mt][nt][rr * 2 + 0] + bias[col];
                    v.y = acc[mt][nt][rr * 2 + 1] + bias[col + 1];
                    *(float2*)(out + (size_t)m * NN + col) = v;
                }
            }
        }
    }
}

// ---------------------------------------------------------------------------
// Flash attention, tf32 tensor cores.
// CTA: 64 q-rows, 4 warps (16 rows each). KV tile = 64.
// Q fragments live in registers for the whole kernel.
// K smem stride 68 (conflict-free B-frags), V stride 72 (conflict-free).
// P is staged through the (dead) K smem region, one 16-row slab per warp.
// grid: (SEQ/64, BH), 128 threads.
// ---------------------------------------------------------------------------
__global__ __launch_bounds__(128)
void attn_mma()
{
    constexpr int BQ = 64, BKV = 64, SK = 68, SV = 72;
    __shared__ float Ks[BKV * SK];   // K tile; later aliased as P slabs
    __shared__ float Vs[BKV * SV];

    const int tid = threadIdx.x, warp = tid >> 5, lane = tid & 31;
    const int g = lane >> 2, t = lane & 3;
    const int bh = blockIdx.y;
    const int q0 = blockIdx.x * BQ + warp * 16;

    // Q fragments (already tf32-rounded, pre-scaled)
    unsigned qf[8][4];
    {
        const float* Qb = g_q + ((size_t)bh * SEQ + q0) * D;
#pragma unroll
        for (int kk = 0; kk < 8; kk++) {
            qf[kk][0] = __float_as_uint(Qb[g * D + kk * 8 + t]);
            qf[kk][1] = __float_as_uint(Qb[(g + 8) * D + kk * 8 + t]);
            qf[kk][2] = __float_as_uint(Qb[g * D + kk * 8 + t + 4]);
            qf[kk][3] = __float_as_uint(Qb[(g + 8) * D + kk * 8 + t + 4]);
        }
    }

    float o[8][4];
#pragma unroll
    for (int nt = 0; nt < 8; nt++)
#pragma unroll
        for (int j = 0; j < 4; j++) o[nt][j] = 0.f;
    float mr0 = -1e30f, mr1 = -1e30f, l0 = 0.f, l1 = 0.f;

    const float* Kb = g_k + (size_t)bh * SEQ * D;
    const float* Vb = g_v + (size_t)bh * SEQ * D;
    float* Pw = Ks + warp * 16 * SK;

    for (int kv = 0; kv < SEQ; kv += BKV) {
        // load K,V tiles (coalesced float4)
#pragma unroll
        for (int i = 0; i < 8; i++) {
            const int idx = tid + i * 128;          // 0..1023
            const int row = idx >> 4, c4 = (idx & 15) << 2;
            *(float4*)&Ks[row * SK + c4] = *(const float4*)&Kb[(kv + row) * D + c4];
            *(float4*)&Vs[row * SV + c4] = *(const float4*)&Vb[(kv + row) * D + c4];
        }
        __syncthreads();

        // S = Q K^T  (16 x 64 per warp)
        float s[8][4];
#pragma unroll
        for (int nt = 0; nt < 8; nt++)
#pragma unroll
            for (int j = 0; j < 4; j++) s[nt][j] = 0.f;
#pragma unroll
        for (int kk = 0; kk < 8; kk++) {
            unsigned bf[8][2];
#pragma unroll
            for (int nt = 0; nt < 8; nt++) {
                const int r = (nt * 8 + g) * SK + kk * 8 + t;
                bf[nt][0] = __float_as_uint(Ks[r]);
                bf[nt][1] = __float_as_uint(Ks[r + 4]);
            }
#pragma unroll
            for (int nt = 0; nt < 8; nt++) mma8(s[nt], qf[kk], bf[nt]);
        }

        // online softmax (rows g and g+8)
        float mn0 = mr0, mn1 = mr1;
#pragma unroll
        for (int nt = 0; nt < 8; nt++) {
            mn0 = fmaxf(mn0, fmaxf(s[nt][0], s[nt][1]));
            mn1 = fmaxf(mn1, fmaxf(s[nt][2], s[nt][3]));
        }
        mn0 = fmaxf(mn0, __shfl_xor_sync(0xffffffffu, mn0, 1));
        mn0 = fmaxf(mn0, __shfl_xor_sync(0xffffffffu, mn0, 2));
        mn1 = fmaxf(mn1, __shfl_xor_sync(0xffffffffu, mn1, 1));
        mn1 = fmaxf(mn1, __shfl_xor_sync(0xffffffffu, mn1, 2));
        const float a0 = __expf(mr0 - mn0);
        const float a1 = __expf(mr1 - mn1);
        mr0 = mn0; mr1 = mn1;
        float ps0 = 0.f, ps1 = 0.f;
#pragma unroll
        for (int nt = 0; nt < 8; nt++) {
            s[nt][0] = __expf(s[nt][0] - mn0);
            s[nt][1] = __expf(s[nt][1] - mn0);
            s[nt][2] = __expf(s[nt][2] - mn1);
            s[nt][3] = __expf(s[nt][3] - mn1);
            ps0 += s[nt][0] + s[nt][1];
            ps1 += s[nt][2] + s[nt][3];
        }
        ps0 += __shfl_xor_sync(0xffffffffu, ps0, 1);
        ps0 += __shfl_xor_sync(0xffffffffu, ps0, 2);
        ps1 += __shfl_xor_sync(0xffffffffu, ps1, 1);
        ps1 += __shfl_xor_sync(0xffffffffu, ps1, 2);
        l0 = l0 * a0 + ps0;
        l1 = l1 * a1 + ps1;
#pragma unroll
        for (int nt = 0; nt < 8; nt++) {
            o[nt][0] *= a0; o[nt][1] *= a0;
            o[nt][2] *= a1; o[nt][3] *= a1;
        }

        __syncthreads();   // everyone done reading K tile

        // stage P into per-warp slab of K region (tf32-rounded)
#pragma unroll
        for (int nt = 0; nt < 8; nt++) {
            float2 v0, v1;
            v0.x = tf32r(s[nt][0]); v0.y = tf32r(s[nt][1]);
            v1.x = tf32r(s[nt][2]); v1.y = tf32r(s[nt][3]);
            *(float2*)&Pw[g * SK + nt * 8 + 2 * t] = v0;
            *(float2*)&Pw[(g + 8) * SK + nt * 8 + 2 * t] = v1;
        }
        __syncwarp();

        // O += P V
#pragma unroll
        for (int kk = 0; kk < 8; kk++) {
            unsigned af[4];
            const int r0 = g * SK + kk * 8 + t;
            const int r1 = (g + 8) * SK + kk * 8 + t;
            af[0] = __float_as_uint(Pw[r0]);
            af[1] = __float_as_uint(Pw[r1]);
            af[2] = __float_as_uint(Pw[r0 + 4]);
            af[3] = __float_as_uint(Pw[r1 + 4]);
#pragma unroll
            for (int nt = 0; nt < 8; nt++) {
                unsigned bf[2];
                bf[0] = __float_as_uint(Vs[(kk * 8 + t) * SV + nt * 8 + g]);
                bf[1] = __float_as_uint(Vs[(kk * 8 + t + 4) * SV + nt * 8 + g]);
                mma8(o[nt], af, bf);
            }
        }
        __syncthreads();   // protect K(P)/V before next tile load
    }

    // normalize + write g_o as [B,N,C]
    const float i0 = 1.f / l0, i1 = 1.f / l1;
    const int b = bh >> 4, h = bh & 15;
    float* Ob = g_o + ((size_t)(b * SEQ) + q0) * C + h * D;
#pragma unroll
    for (int nt = 0; nt < 8; nt++) {
        float2 v0, v1;
        v0.x = o[nt][0] * i0; v0.y = o[nt][1] * i0;
        v1.x = o[nt][2] * i1; v1.y = o[nt][3] * i1;
        *(float2*)&Ob[g * C + nt * 8 + 2 * t] = v0;
        *(float2*)&Ob[(g + 8) * C + nt * 8 + 2 * t] = v1;
    }
}

// ---------------------------------------------------------------------------
extern "C" void kernel_launch(void* const* d_in, const int* in_sizes, int n_in,
                              void* d_out, int out_size)
{
    const float* x      = (const float*)d_in[0];   // [B,N,C]
    const float* w_qkv  = (const float*)d_in[1];   // [3C, C]
    const float* w_proj = (const float*)d_in[2];   // [C, C]
    const float* b_proj = (const float*)d_in[3];   // [C]
    float* out = (float*)d_out;                    // [B,N,C]

    // 1) QKV projection -> g_q (scaled), g_k, g_v (all tf32-rounded)
    gemm_mma<0, 3 * C><<<dim3(3 * C / 128, MTOT / 128), 256>>>(x, w_qkv, nullptr, nullptr);

    // 2) attention -> g_o [B,N,C]
    attn_mma<<<dim3(SEQ / 64, BH), 128>>>();

    // 3) output projection + bias -> out
    gemm_mma<1, C><<<dim3(C / 128, MTOT / 128), 256>>>(nullptr, w_proj, b_proj, out);
}

// round 4
// speedup vs baseline: 3.7255x; 1.1338x over previous
#include <cuda_runtime.h>

// Problem constants
constexpr int B    = 2;
constexpr int SEQ  = 2048;
constexpr int C    = 1024;
constexpr int H    = 16;
constexpr int D    = 64;
constexpr int BH   = B * H;       // 32
constexpr int MTOT = B * SEQ;     // 4096
constexpr int KDIM = C;

// Scratch (allocation-free rule: __device__ globals)
__device__ float g_q[BH * SEQ * D];     // tf32-rounded, pre-scaled
__device__ float g_k[BH * SEQ * D];     // tf32-rounded
__device__ float g_v[BH * SEQ * D];     // tf32-rounded
__device__ float g_o[MTOT * C];         // attention out, tf32-rounded
__device__ float g_xr[MTOT * C];        // x, tf32-rounded
__device__ float g_wqkv[3 * C * C];     // w_qkv, tf32-rounded
__device__ float g_wproj[C * C];        // w_proj, tf32-rounded

__device__ __forceinline__ float tf32r(float x) {
    asm("cvt.rna.tf32.f32 %0, %0;" : "+f"(x));
    return x;
}

__device__ __forceinline__ void mma8(float* d, const unsigned* a, const unsigned* b) {
    asm volatile(
        "mma.sync.aligned.m16n8k8.row.col.f32.tf32.tf32.f32 "
        "{%0,%1,%2,%3}, {%4,%5,%6,%7}, {%8,%9}, {%0,%1,%2,%3};\n"
        : "+f"(d[0]), "+f"(d[1]), "+f"(d[2]), "+f"(d[3])
        : "r"(a[0]), "r"(a[1]), "r"(a[2]), "r"(a[3]), "r"(b[0]), "r"(b[1]));
}

__device__ __forceinline__ void cpa16(float* dst, const float* src) {
    unsigned d = (unsigned)__cvta_generic_to_shared(dst);
    asm volatile("cp.async.cg.shared.global [%0], [%1], 16;\n" :: "r"(d), "l"(src));
}
__device__ __forceinline__ void cpcommit() { asm volatile("cp.async.commit_group;\n"); }
template <int N> __device__ __forceinline__ void cpwait() {
    asm volatile("cp.async.wait_group %0;\n" :: "n"(N));
}

// ---------------------------------------------------------------------------
// Prepass: tf32-round a buffer (float4 granularity)
// ---------------------------------------------------------------------------
__global__ void round_copy(const float* __restrict__ src, float* __restrict__ dst) {
    const int i = blockIdx.x * blockDim.x + threadIdx.x;
    float4 v = ((const float4*)src)[i];
    v.x = tf32r(v.x); v.y = tf32r(v.y); v.z = tf32r(v.z); v.w = tf32r(v.w);
    ((float4*)dst)[i] = v;
}

// ---------------------------------------------------------------------------
// tf32 GEMM (NT), 3-stage cp.async pipeline. Y[m,j] = sum_k A[m,k]*W[j,k]
// Tile 128x128x16, 256 thr (8 warps 2x4), warp tile 64x32, smem stride 20.
// MODE 0: scatter -> g_q (scaled+rounded), g_k, g_v.  MODE 1: bias, out.
// ---------------------------------------------------------------------------
template <int MODE, int NN>
__global__ __launch_bounds__(256)
void gemm_mma(const float* __restrict__ A, const float* __restrict__ W,
              const float* __restrict__ bias, float* __restrict__ out)
{
    constexpr int BM = 128, BK = 16, SA = BK + 4, STG = 3;
    constexpr int ASZ = BM * SA;
    extern __shared__ float sm[];
    float* As = sm;                              // [STG][ASZ]
    float* Bs = sm + STG * ASZ;                  // [STG][ASZ]

    const int tid  = threadIdx.x;
    const int warp = tid >> 5, lane = tid & 31;
    const int g = lane >> 2, t = lane & 3;
    const int wm = (warp >> 2) * 64;
    const int wn = (warp & 3) * 32;
    const int m0 = blockIdx.y * BM;
    const int n0 = blockIdx.x * BM;

    const int lrow = tid >> 2;            // 0..63
    const int lcol = (tid & 3) << 2;      // 0,4,8,12
    const float* aptr = A + (size_t)(m0 + lrow) * KDIM + lcol;
    const float* wptr = W + (size_t)(n0 + lrow) * KDIM + lcol;

    auto issue = [&](int kt, int buf) {
        const int k0 = kt * BK;
        float* a = As + buf * ASZ;
        float* b = Bs + buf * ASZ;
        cpa16(a + lrow * SA + lcol,        aptr + k0);
        cpa16(a + (lrow + 64) * SA + lcol, aptr + 64 * KDIM + k0);
        cpa16(b + lrow * SA + lcol,        wptr + k0);
        cpa16(b + (lrow + 64) * SA + lcol, wptr + 64 * KDIM + k0);
    };

    float acc[4][4][4];
#pragma unroll
    for (int mt = 0; mt < 4; mt++)
#pragma unroll
        for (int nt = 0; nt < 4; nt++)
#pragma unroll
            for (int j = 0; j < 4; j++) acc[mt][nt][j] = 0.f;

    constexpr int KT = KDIM / BK;  // 64
    issue(0, 0); cpcommit();
    issue(1, 1); cpcommit();

    for (int kt = 0; kt < KT; ++kt) {
        cpwait<1>();
        __syncthreads();
        if (kt + 2 < KT) issue(kt + 2, (kt + 2) % STG);
        cpcommit();

        const float* a = As + (kt % STG) * ASZ;
        const float* b = Bs + (kt % STG) * ASZ;
#pragma unroll
        for (int ks = 0; ks < 2; ks++) {
            const int k0 = ks * 8;
            unsigned af[4][4], bf[4][2];
#pragma unroll
            for (int mt = 0; mt < 4; mt++) {
                const int r0 = (wm + mt * 16 + g) * SA + k0 + t;
                const int r1 = (wm + mt * 16 + g + 8) * SA + k0 + t;
                af[mt][0] = __float_as_uint(a[r0]);
                af[mt][1] = __float_as_uint(a[r1]);
                af[mt][2] = __float_as_uint(a[r0 + 4]);
                af[mt][3] = __float_as_uint(a[r1 + 4]);
            }
#pragma unroll
            for (int nt = 0; nt < 4; nt++) {
                const int r = (wn + nt * 8 + g) * SA + k0 + t;
                bf[nt][0] = __float_as_uint(b[r]);
                bf[nt][1] = __float_as_uint(b[r + 4]);
            }
#pragma unroll
            for (int mt = 0; mt < 4; mt++)
#pragma unroll
                for (int nt = 0; nt < 4; nt++)
                    mma8(acc[mt][nt], af[mt], bf[nt]);
        }
    }

    // -------- epilogue --------
    if (MODE == 0) {
#pragma unroll
        for (int mt = 0; mt < 4; mt++) {
#pragma unroll
            for (int rr = 0; rr < 2; rr++) {
                const int m = m0 + wm + mt * 16 + g + rr * 8;
                const int b = m >> 11;
                const int n = m & 2047;
#pragma unroll
                for (int nt = 0; nt < 4; nt++) {
#pragma unroll
                    for (int j = 0; j < 2; j++) {
                        const int col = n0 + wn + nt * 8 + 2 * t + j;
                        const float v = acc[mt][nt][rr * 2 + j];
                        const int which = col >> 10;
                        const int r = col & 1023;
                        const int h = r >> 6;
                        const int d = r & 63;
                        const size_t idx = ((size_t)((b * H + h) * SEQ + n)) * D + d;
                        if (which == 0)      g_q[idx] = tf32r(v * 0.125f);
                        else if (which == 1) g_k[idx] = tf32r(v);
                        else                 g_v[idx] = tf32r(v);
                    }
                }
            }
        }
    } else {
#pragma unroll
        for (int mt = 0; mt < 4; mt++) {
#pragma unroll
            for (int rr = 0; rr < 2; rr++) {
                const int m = m0 + wm + mt * 16 + g + rr * 8;
#pragma unroll
                for (int nt = 0; nt < 4; nt++) {
                    const int col = n0 + wn + nt * 8 + 2 * t;
                    float2 v;
                    v.x = acc[mt][nt][rr * 2 + 0] + bias[col];
                    v.y = acc[mt][nt][rr * 2 + 1] + bias[col + 1];
                    *(float2*)(out + (size_t)m * NN + col) = v;
                }
            }
        }
    }
}

// ---------------------------------------------------------------------------
// Flash attention, tf32 MMA, cp.async double-buffered K/V.
// CTA: 64 q-rows, 4 warps (16 each). KV tile 64. Q frags in regs.
// K stride 68, V stride 72 (conflict-free). P staged in dead K region.
// ---------------------------------------------------------------------------
__global__ __launch_bounds__(128)
void attn_mma()
{
    constexpr int BQ = 64, BKV = 64, SK = 68, SV = 72;
    constexpr int KSZ = BKV * SK, VSZ = BKV * SV;
    extern __shared__ float sm[];
    float* K0 = sm;                     // [2][KSZ]
    float* V0 = sm + 2 * KSZ;           // [2][VSZ]

    const int tid = threadIdx.x, warp = tid >> 5, lane = tid & 31;
    const int g = lane >> 2, t = lane & 3;
    const int bh = blockIdx.y;
    const int q0 = blockIdx.x * BQ + warp * 16;

    const float* Kb = g_k + (size_t)bh * SEQ * D;
    const float* Vb = g_v + (size_t)bh * SEQ * D;

    // loader: 64 rows x 16 float4-chunks = 1024 chunks per matrix per tile;
    // 128 threads -> 8 chunks each. row = idx>>4 (0..63), c4 = (idx&15)*4.
    auto issue_kv = [&](int tile, int buf) {
        const float* ks = Kb + tile * (BKV * D);
        const float* vs = Vb + tile * (BKV * D);
        float* kd = K0 + buf * KSZ;
        float* vd = V0 + buf * VSZ;
#pragma unroll
        for (int i = 0; i < 8; i++) {
            const int idx = tid + i * 128;               // 0..1023
            const int row = idx >> 4, c4 = (idx & 15) << 2;
            cpa16(kd + row * SK + c4, ks + row * D + c4);
            cpa16(vd + row * SV + c4, vs + row * D + c4);
        }
    };

    // Q fragments (pre-rounded, pre-scaled)
    unsigned qf[8][4];
    {
        const float* Qb = g_q + ((size_t)bh * SEQ + q0) * D;
#pragma unroll
        for (int kk = 0; kk < 8; kk++) {
            qf[kk][0] = __float_as_uint(Qb[g * D + kk * 8 + t]);
            qf[kk][1] = __float_as_uint(Qb[(g + 8) * D + kk * 8 + t]);
            qf[kk][2] = __float_as_uint(Qb[g * D + kk * 8 + t + 4]);
            qf[kk][3] = __float_as_uint(Qb[(g + 8) * D + kk * 8 + t + 4]);
        }
    }

    float o[8][4];
#pragma unroll
    for (int nt = 0; nt < 8; nt++)
#pragma unroll
        for (int j = 0; j < 4; j++) o[nt][j] = 0.f;
    float mr0 = -1e30f, mr1 = -1e30f, l0 = 0.f, l1 = 0.f;

    constexpr int NT = SEQ / BKV;
    issue_kv(0, 0); cpcommit();

    for (int tile = 0; tile < NT; ++tile) {
        cpwait<0>();
        __syncthreads();
        if (tile + 1 < NT) issue_kv(tile + 1, (tile + 1) & 1);
        cpcommit();

        float* Ks = K0 + (tile & 1) * KSZ;
        float* Vs = V0 + (tile & 1) * VSZ;
        float* Pw = Ks + warp * 16 * SK;

        // S = Q K^T  (16 x 64 per warp)
        float s[8][4];
#pragma unroll
        for (int nt = 0; nt < 8; nt++)
#pragma unroll
            for (int j = 0; j < 4; j++) s[nt][j] = 0.f;
#pragma unroll
        for (int kk = 0; kk < 8; kk++) {
            unsigned bf[8][2];
#pragma unroll
            for (int nt = 0; nt < 8; nt++) {
                const int r = (nt * 8 + g) * SK + kk * 8 + t;
                bf[nt][0] = __float_as_uint(Ks[r]);
                bf[nt][1] = __float_as_uint(Ks[r + 4]);
            }
#pragma unroll
            for (int nt = 0; nt < 8; nt++) mma8(s[nt], qf[kk], bf[nt]);
        }

        // online softmax
        float mn0 = mr0, mn1 = mr1;
#pragma unroll
        for (int nt = 0; nt < 8; nt++) {
            mn0 = fmaxf(mn0, fmaxf(s[nt][0], s[nt][1]));
            mn1 = fmaxf(mn1, fmaxf(s[nt][2], s[nt][3]));
        }
        mn0 = fmaxf(mn0, __shfl_xor_sync(0xffffffffu, mn0, 1));
        mn0 = fmaxf(mn0, __shfl_xor_sync(0xffffffffu, mn0, 2));
        mn1 = fmaxf(mn1, __shfl_xor_sync(0xffffffffu, mn1, 1));
        mn1 = fmaxf(mn1, __shfl_xor_sync(0xffffffffu, mn1, 2));
        const float a0 = __expf(mr0 - mn0);
        const float a1 = __expf(mr1 - mn1);
        mr0 = mn0; mr1 = mn1;
        float ps0 = 0.f, ps1 = 0.f;
#pragma unroll
        for (int nt = 0; nt < 8; nt++) {
            s[nt][0] = __expf(s[nt][0] - mn0);
            s[nt][1] = __expf(s[nt][1] - mn0);
            s[nt][2] = __expf(s[nt][2] - mn1);
            s[nt][3] = __expf(s[nt][3] - mn1);
            ps0 += s[nt][0] + s[nt][1];
            ps1 += s[nt][2] + s[nt][3];
        }
        ps0 += __shfl_xor_sync(0xffffffffu, ps0, 1);
        ps0 += __shfl_xor_sync(0xffffffffu, ps0, 2);
        ps1 += __shfl_xor_sync(0xffffffffu, ps1, 1);
        ps1 += __shfl_xor_sync(0xffffffffu, ps1, 2);
        l0 = l0 * a0 + ps0;
        l1 = l1 * a1 + ps1;
#pragma unroll
        for (int nt = 0; nt < 8; nt++) {
            o[nt][0] *= a0; o[nt][1] *= a0;
            o[nt][2] *= a1; o[nt][3] *= a1;
        }

        __syncthreads();   // all warps done reading K tile

        // stage P into this warp's slab of the (dead) K region
#pragma unroll
        for (int nt = 0; nt < 8; nt++) {
            float2 v0, v1;
            v0.x = tf32r(s[nt][0]); v0.y = tf32r(s[nt][1]);
            v1.x = tf32r(s[nt][2]); v1.y = tf32r(s[nt][3]);
            *(float2*)&Pw[g * SK + nt * 8 + 2 * t] = v0;
            *(float2*)&Pw[(g + 8) * SK + nt * 8 + 2 * t] = v1;
        }
        __syncwarp();

        // O += P V
#pragma unroll
        for (int kk = 0; kk < 8; kk++) {
            unsigned af[4];
            const int r0 = g * SK + kk * 8 + t;
            const int r1 = (g + 8) * SK + kk * 8 + t;
            af[0] = __float_as_uint(Pw[r0]);
            af[1] = __float_as_uint(Pw[r1]);
            af[2] = __float_as_uint(Pw[r0 + 4]);
            af[3] = __float_as_uint(Pw[r1 + 4]);
#pragma unroll
            for (int nt = 0; nt < 8; nt++) {
                unsigned bf[2];
                bf[0] = __float_as_uint(Vs[(kk * 8 + t) * SV + nt * 8 + g]);
                bf[1] = __float_as_uint(Vs[(kk * 8 + t + 4) * SV + nt * 8 + g]);
                mma8(o[nt], af, bf);
            }
        }
    }

    // normalize + write g_o (tf32-rounded for the proj GEMM)
    const float i0 = 1.f / l0, i1 = 1.f / l1;
    const int b = bh >> 4, h = bh & 15;
    float* Ob = g_o + ((size_t)(b * SEQ) + q0) * C + h * D;
#pragma unroll
    for (int nt = 0; nt < 8; nt++) {
        float2 v0, v1;
        v0.x = tf32r(o[nt][0] * i0); v0.y = tf32r(o[nt][1] * i0);
        v1.x = tf32r(o[nt][2] * i1); v1.y = tf32r(o[nt][3] * i1);
        *(float2*)&Ob[g * C + nt * 8 + 2 * t] = v0;
        *(float2*)&Ob[(g + 8) * C + nt * 8 + 2 * t] = v1;
    }
}

// ---------------------------------------------------------------------------
extern "C" void kernel_launch(void* const* d_in, const int* in_sizes, int n_in,
                              void* d_out, int out_size)
{
    const float* x      = (const float*)d_in[0];
    const float* w_qkv  = (const float*)d_in[1];
    const float* w_proj = (const float*)d_in[2];
    const float* b_proj = (const float*)d_in[3];
    float* out = (float*)d_out;

    constexpr int GEMM_SMEM = 3 * 2 * 128 * 20 * 4;           // 61440
    constexpr int ATTN_SMEM = 2 * 64 * (68 + 72) * 4;         // 71680
    cudaFuncSetAttribute(gemm_mma<0, 3 * C>, cudaFuncAttributeMaxDynamicSharedMemorySize, GEMM_SMEM);
    cudaFuncSetAttribute(gemm_mma<1, C>,     cudaFuncAttributeMaxDynamicSharedMemorySize, GEMM_SMEM);
    cudaFuncSetAttribute(attn_mma,           cudaFuncAttributeMaxDynamicSharedMemorySize, ATTN_SMEM);

    float* xr = nullptr, *wq = nullptr, *wp = nullptr;
    cudaGetSymbolAddress((void**)&xr, g_xr);
    cudaGetSymbolAddress((void**)&wq, g_wqkv);
    cudaGetSymbolAddress((void**)&wp, g_wproj);

    // 0) tf32-round inputs once
    round_copy<<<(MTOT * C / 4) / 256, 256>>>(x, xr);
    round_copy<<<(3 * C * C / 4) / 256, 256>>>(w_qkv, wq);
    round_copy<<<(C * C / 4) / 256, 256>>>(w_proj, wp);

    // 1) QKV projection
    gemm_mma<0, 3 * C><<<dim3(3 * C / 128, MTOT / 128), 256, GEMM_SMEM>>>(xr, wq, nullptr, nullptr);

    // 2) attention
    attn_mma<<<dim3(SEQ / 64, BH), 128, ATTN_SMEM>>>();

    // 3) output projection + bias
    float* go = nullptr;
    cudaGetSymbolAddress((void**)&go, g_o);
    gemm_mma<1, C><<<dim3(C / 128, MTOT / 128), 256, GEMM_SMEM>>>(go, wp, b_proj, out);
}

// round 6
// speedup vs baseline: 3.7968x; 1.0191x over previous
#include <cuda_runtime.h>
#include <cstdint>

// Problem constants
constexpr int B    = 2;
constexpr int SEQ  = 2048;
constexpr int C    = 1024;
constexpr int H    = 16;
constexpr int D    = 64;
constexpr int BH   = B * H;       // 32
constexpr int MTOT = B * SEQ;     // 4096
constexpr int KDIM = C;

// Scratch (allocation-free rule: __device__ globals)
__device__ float g_q[BH * SEQ * D];     // tf32-rounded, pre-scaled
__device__ float g_k[BH * SEQ * D];     // tf32-rounded
__device__ float g_v[BH * SEQ * D];     // tf32-rounded
__device__ float g_o[MTOT * C];         // attention out, tf32-rounded
__device__ float g_xr[MTOT * C];        // x, tf32-rounded
__device__ float g_wqkv[3 * C * C];     // w_qkv, tf32-rounded
__device__ float g_wproj[C * C];        // w_proj, tf32-rounded

__device__ __forceinline__ float tf32r(float x) {
    asm("cvt.rna.tf32.f32 %0, %0;" : "+f"(x));
    return x;
}

__device__ __forceinline__ void mma8(float* d, const unsigned* a, const unsigned* b) {
    asm volatile(
        "mma.sync.aligned.m16n8k8.row.col.f32.tf32.tf32.f32 "
        "{%0,%1,%2,%3}, {%4,%5,%6,%7}, {%8,%9}, {%0,%1,%2,%3};\n"
        : "+f"(d[0]), "+f"(d[1]), "+f"(d[2]), "+f"(d[3])
        : "r"(a[0]), "r"(a[1]), "r"(a[2]), "r"(a[3]), "r"(b[0]), "r"(b[1]));
}

__device__ __forceinline__ void cpa16(float* dst, const float* src) {
    unsigned d = (unsigned)__cvta_generic_to_shared(dst);
    asm volatile("cp.async.cg.shared.global [%0], [%1], 16;\n" :: "r"(d), "l"(src));
}
__device__ __forceinline__ void cpcommit() { asm volatile("cp.async.commit_group;\n"); }
template <int N> __device__ __forceinline__ void cpwait() {
    asm volatile("cp.async.wait_group %0;\n" :: "n"(N));
}

// ---------------------------------------------------------------------------
// Prepass: tf32-round a buffer (float4 granularity)
// ---------------------------------------------------------------------------
__global__ void round_copy(const float* __restrict__ src, float* __restrict__ dst) {
    const int i = blockIdx.x * blockDim.x + threadIdx.x;
    float4 v = ((const float4*)src)[i];
    v.x = tf32r(v.x); v.y = tf32r(v.y); v.z = tf32r(v.z); v.w = tf32r(v.w);
    ((float4*)dst)[i] = v;
}

// ---------------------------------------------------------------------------
// tf32 GEMM (NT), 3-stage cp.async. Y[m,j] = sum_k A[m,k]*W[j,k]
// CTA tile 256x128x16, 256 thr, 8 warps (4x2), warp tile 64x64.
// 64 MMAs / warp / k-tile between barriers; 1 LDS per MMA.
// MODE 0: scatter -> g_q (scaled+rounded), g_k, g_v.  MODE 1: bias, out.
// ---------------------------------------------------------------------------
template <int MODE, int NN>
__global__ __launch_bounds__(256, 1)
void gemm_mma(const float* __restrict__ A, const float* __restrict__ W,
              const float* __restrict__ bias, float* __restrict__ out)
{
    constexpr int BM = 256, BN = 128, BK = 16, SA = BK + 4, STG = 3;
    constexpr int ASZ = BM * SA;                 // 5120 floats per stage
    constexpr int BSZ = BN * SA;                 // 2560 floats per stage
    extern __shared__ float sm[];
    float* As = sm;                              // [STG][ASZ]
    float* Bs = sm + STG * ASZ;                  // [STG][BSZ]

    const int tid  = threadIdx.x;
    const int warp = tid >> 5, lane = tid & 31;
    const int g = lane >> 2, t = lane & 3;
    const int wm = (warp >> 1) * 64;             // 0,64,128,192
    const int wn = (warp & 1) * 64;              // 0,64
    const int m0 = blockIdx.y * BM;
    const int n0 = blockIdx.x * BN;

    // A loader: 256 rows x 4 chunks; B loader: 128 rows x 4 chunks
    const int arow = tid >> 2;                   // 0..63 (+64 steps)
    const int acol = (tid & 3) << 2;             // 0,4,8,12
    const float* aptr = A + (size_t)(m0 + arow) * KDIM + acol;
    const float* wptr = W + (size_t)(n0 + arow) * KDIM + acol;

    auto issue = [&](int kt, int buf) {
        const int k0 = kt * BK;
        float* a = As + buf * ASZ;
        float* b = Bs + buf * BSZ;
#pragma unroll
        for (int j = 0; j < 4; j++)
            cpa16(a + (arow + 64 * j) * SA + acol, aptr + (size_t)(64 * j) * KDIM + k0);
#pragma unroll
        for (int j = 0; j < 2; j++)
            cpa16(b + (arow + 64 * j) * SA + acol, wptr + (size_t)(64 * j) * KDIM + k0);
    };

    float acc[4][8][4];
#pragma unroll
    for (int mt = 0; mt < 4; mt++)
#pragma unroll
        for (int nt = 0; nt < 8; nt++)
#pragma unroll
            for (int j = 0; j < 4; j++) acc[mt][nt][j] = 0.f;

    constexpr int KT = KDIM / BK;  // 64
    issue(0, 0); cpcommit();
    issue(1, 1); cpcommit();

    for (int kt = 0; kt < KT; ++kt) {
        cpwait<1>();
        __syncthreads();
        if (kt + 2 < KT) issue(kt + 2, (kt + 2) % STG);
        cpcommit();

        const float* a = As + (kt % STG) * ASZ;
        const float* b = Bs + (kt % STG) * BSZ;
#pragma unroll
        for (int ks = 0; ks < 2; ks++) {
            const int k0 = ks * 8;
            unsigned af[4][4], bf[8][2];
#pragma unroll
            for (int mt = 0; mt < 4; mt++) {
                const int r0 = (wm + mt * 16 + g) * SA + k0 + t;
                const int r1 = (wm + mt * 16 + g + 8) * SA + k0 + t;
                af[mt][0] = __float_as_uint(a[r0]);
                af[mt][1] = __float_as_uint(a[r1]);
                af[mt][2] = __float_as_uint(a[r0 + 4]);
                af[mt][3] = __float_as_uint(a[r1 + 4]);
            }
#pragma unroll
            for (int nt = 0; nt < 8; nt++) {
                const int r = (wn + nt * 8 + g) * SA + k0 + t;
                bf[nt][0] = __float_as_uint(b[r]);
                bf[nt][1] = __float_as_uint(b[r + 4]);
            }
#pragma unroll
            for (int mt = 0; mt < 4; mt++)
#pragma unroll
                for (int nt = 0; nt < 8; nt++)
                    mma8(acc[mt][nt], af[mt], bf[nt]);
        }
    }

    // -------- epilogue --------
    if (MODE == 0) {
#pragma unroll
        for (int mt = 0; mt < 4; mt++) {
#pragma unroll
            for (int rr = 0; rr < 2; rr++) {
                const int m = m0 + wm + mt * 16 + g + rr * 8;
                const int b = m >> 11;
                const int n = m & 2047;
#pragma unroll
                for (int nt = 0; nt < 8; nt++) {
#pragma unroll
                    for (int j = 0; j < 2; j++) {
                        const int col = n0 + wn + nt * 8 + 2 * t + j;
                        const float v = acc[mt][nt][rr * 2 + j];
                        const int which = col >> 10;
                        const int r = col & 1023;
                        const int h = r >> 6;
                        const int d = r & 63;
                        const size_t idx = ((size_t)((b * H + h) * SEQ + n)) * D + d;
                        if (which == 0)      g_q[idx] = tf32r(v * 0.125f);
                        else if (which == 1) g_k[idx] = tf32r(v);
                        else                 g_v[idx] = tf32r(v);
                    }
                }
            }
        }
    } else {
#pragma unroll
        for (int mt = 0; mt < 4; mt++) {
#pragma unroll
            for (int rr = 0; rr < 2; rr++) {
                const int m = m0 + wm + mt * 16 + g + rr * 8;
#pragma unroll
                for (int nt = 0; nt < 8; nt++) {
                    const int col = n0 + wn + nt * 8 + 2 * t;
                    float2 v;
                    v.x = acc[mt][nt][rr * 2 + 0] + bias[col];
                    v.y = acc[mt][nt][rr * 2 + 1] + bias[col + 1];
                    *(float2*)(out + (size_t)m * NN + col) = v;
                }
            }
        }
    }
}

// ---------------------------------------------------------------------------
// Flash attention, tf32 MMA, cp.async double-buffered K/V (round-4 version).
// ---------------------------------------------------------------------------
__global__ __launch_bounds__(128)
void attn_mma()
{
    constexpr int BQ = 64, BKV = 64, SK = 68, SV = 72;
    constexpr int KSZ = BKV * SK, VSZ = BKV * SV;
    extern __shared__ float sm[];
    float* K0 = sm;
    float* V0 = sm + 2 * KSZ;

    const int tid = threadIdx.x, warp = tid >> 5, lane = tid & 31;
    const int g = lane >> 2, t = lane & 3;
    const int bh = blockIdx.y;
    const int q0 = blockIdx.x * BQ + warp * 16;

    const float* Kb = g_k + (size_t)bh * SEQ * D;
    const float* Vb = g_v + (size_t)bh * SEQ * D;

    auto issue_kv = [&](int tile, int buf) {
        const float* ks = Kb + tile * (BKV * D);
        const float* vs = Vb + tile * (BKV * D);
        float* kd = K0 + buf * KSZ;
        float* vd = V0 + buf * VSZ;
#pragma unroll
        for (int i = 0; i < 8; i++) {
            const int idx = tid + i * 128;
            const int row = idx >> 4, c4 = (idx & 15) << 2;
            cpa16(kd + row * SK + c4, ks + row * D + c4);
            cpa16(vd + row * SV + c4, vs + row * D + c4);
        }
    };

    unsigned qf[8][4];
    {
        const float* Qb = g_q + ((size_t)bh * SEQ + q0) * D;
#pragma unroll
        for (int kk = 0; kk < 8; kk++) {
            qf[kk][0] = __float_as_uint(Qb[g * D + kk * 8 + t]);
            qf[kk][1] = __float_as_uint(Qb[(g + 8) * D + kk * 8 + t]);
            qf[kk][2] = __float_as_uint(Qb[g * D + kk * 8 + t + 4]);
            qf[kk][3] = __float_as_uint(Qb[(g + 8) * D + kk * 8 + t + 4]);
        }
    }

    float o[8][4];
#pragma unroll
    for (int nt = 0; nt < 8; nt++)
#pragma unroll
        for (int j = 0; j < 4; j++) o[nt][j] = 0.f;
    float mr0 = -1e30f, mr1 = -1e30f, l0 = 0.f, l1 = 0.f;

    constexpr int NT = SEQ / BKV;
    issue_kv(0, 0); cpcommit();

    for (int tile = 0; tile < NT; ++tile) {
        cpwait<0>();
        __syncthreads();
        if (tile + 1 < NT) issue_kv(tile + 1, (tile + 1) & 1);
        cpcommit();

        float* Ks = K0 + (tile & 1) * KSZ;
        float* Vs = V0 + (tile & 1) * VSZ;
        float* Pw = Ks + warp * 16 * SK;

        float s[8][4];
#pragma unroll
        for (int nt = 0; nt < 8; nt++)
#pragma unroll
            for (int j = 0; j < 4; j++) s[nt][j] = 0.f;
#pragma unroll
        for (int kk = 0; kk < 8; kk++) {
            unsigned bf[8][2];
#pragma unroll
            for (int nt = 0; nt < 8; nt++) {
                const int r = (nt * 8 + g) * SK + kk * 8 + t;
                bf[nt][0] = __float_as_uint(Ks[r]);
                bf[nt][1] = __float_as_uint(Ks[r + 4]);
            }
#pragma unroll
            for (int nt = 0; nt < 8; nt++) mma8(s[nt], qf[kk], bf[nt]);
        }

        float mn0 = mr0, mn1 = mr1;
#pragma unroll
        for (int nt = 0; nt < 8; nt++) {
            mn0 = fmaxf(mn0, fmaxf(s[nt][0], s[nt][1]));
            mn1 = fmaxf(mn1, fmaxf(s[nt][2], s[nt][3]));
        }
        mn0 = fmaxf(mn0, __shfl_xor_sync(0xffffffffu, mn0, 1));
        mn0 = fmaxf(mn0, __shfl_xor_sync(0xffffffffu, mn0, 2));
        mn1 = fmaxf(mn1, __shfl_xor_sync(0xffffffffu, mn1, 1));
        mn1 = fmaxf(mn1, __shfl_xor_sync(0xffffffffu, mn1, 2));
        const float a0 = __expf(mr0 - mn0);
        const float a1 = __expf(mr1 - mn1);
        mr0 = mn0; mr1 = mn1;
        float ps0 = 0.f, ps1 = 0.f;
#pragma unroll
        for (int nt = 0; nt < 8; nt++) {
            s[nt][0] = __expf(s[nt][0] - mn0);
            s[nt][1] = __expf(s[nt][1] - mn0);
            s[nt][2] = __expf(s[nt][2] - mn1);
            s[nt][3] = __expf(s[nt][3] - mn1);
            ps0 += s[nt][0] + s[nt][1];
            ps1 += s[nt][2] + s[nt][3];
        }
        ps0 += __shfl_xor_sync(0xffffffffu, ps0, 1);
        ps0 += __shfl_xor_sync(0xffffffffu, ps0, 2);
        ps1 += __shfl_xor_sync(0xffffffffu, ps1, 1);
        ps1 += __shfl_xor_sync(0xffffffffu, ps1, 2);
        l0 = l0 * a0 + ps0;
        l1 = l1 * a1 + ps1;
#pragma unroll
        for (int nt = 0; nt < 8; nt++) {
            o[nt][0] *= a0; o[nt][1] *= a0;
            o[nt][2] *= a1; o[nt][3] *= a1;
        }

        __syncthreads();

#pragma unroll
        for (int nt = 0; nt < 8; nt++) {
            float2 v0, v1;
            v0.x = tf32r(s[nt][0]); v0.y = tf32r(s[nt][1]);
            v1.x = tf32r(s[nt][2]); v1.y = tf32r(s[nt][3]);
            *(float2*)&Pw[g * SK + nt * 8 + 2 * t] = v0;
            *(float2*)&Pw[(g + 8) * SK + nt * 8 + 2 * t] = v1;
        }
        __syncwarp();

#pragma unroll
        for (int kk = 0; kk < 8; kk++) {
            unsigned af[4];
            const int r0 = g * SK + kk * 8 + t;
            const int r1 = (g + 8) * SK + kk * 8 + t;
            af[0] = __float_as_uint(Pw[r0]);
            af[1] = __float_as_uint(Pw[r1]);
            af[2] = __float_as_uint(Pw[r0 + 4]);
            af[3] = __float_as_uint(Pw[r1 + 4]);
#pragma unroll
            for (int nt = 0; nt < 8; nt++) {
                unsigned bf[2];
                bf[0] = __float_as_uint(Vs[(kk * 8 + t) * SV + nt * 8 + g]);
                bf[1] = __float_as_uint(Vs[(kk * 8 + t + 4) * SV + nt * 8 + g]);
                mma8(o[nt], af, bf);
            }
        }
    }

    const float i0 = 1.f / l0, i1 = 1.f / l1;
    const int b = bh >> 4, h = bh & 15;
    float* Ob = g_o + ((size_t)(b * SEQ) + q0) * C + h * D;
#pragma unroll
    for (int nt = 0; nt < 8; nt++) {
        float2 v0, v1;
        v0.x = tf32r(o[nt][0] * i0); v0.y = tf32r(o[nt][1] * i0);
        v1.x = tf32r(o[nt][2] * i1); v1.y = tf32r(o[nt][3] * i1);
        *(float2*)&Ob[g * C + nt * 8 + 2 * t] = v0;
        *(float2*)&Ob[(g + 8) * C + nt * 8 + 2 * t] = v1;
    }
}

// ---------------------------------------------------------------------------
extern "C" void kernel_launch(void* const* d_in, const int* in_sizes, int n_in,
                              void* d_out, int out_size)
{
    const float* x      = (const float*)d_in[0];
    const float* w_qkv  = (const float*)d_in[1];
    const float* w_proj = (const float*)d_in[2];
    const float* b_proj = (const float*)d_in[3];
    float* out = (float*)d_out;

    constexpr int GEMM_SMEM = 3 * (256 + 128) * 20 * 4;       // 92160
    constexpr int ATTN_SMEM = 2 * 64 * (68 + 72) * 4;         // 71680
    cudaFuncSetAttribute(gemm_mma<0, 3 * C>, cudaFuncAttributeMaxDynamicSharedMemorySize, GEMM_SMEM);
    cudaFuncSetAttribute(gemm_mma<1, C>,     cudaFuncAttributeMaxDynamicSharedMemorySize, GEMM_SMEM);
    cudaFuncSetAttribute(attn_mma,           cudaFuncAttributeMaxDynamicSharedMemorySize, ATTN_SMEM);

    float* xr = nullptr, *wq = nullptr, *wp = nullptr, *go = nullptr;
    cudaGetSymbolAddress((void**)&xr, g_xr);
    cudaGetSymbolAddress((void**)&wq, g_wqkv);
    cudaGetSymbolAddress((void**)&wp, g_wproj);
    cudaGetSymbolAddress((void**)&go, g_o);

    // 0) tf32-round inputs once
    round_copy<<<(MTOT * C / 4) / 256, 256>>>(x, xr);
    round_copy<<<(3 * C * C / 4) / 256, 256>>>(w_qkv, wq);
    round_copy<<<(C * C / 4) / 256, 256>>>(w_proj, wp);

    // 1) QKV projection
    gemm_mma<0, 3 * C><<<dim3(3 * C / 128, MTOT / 256), 256, GEMM_SMEM>>>(xr, wq, nullptr, nullptr);

    // 2) attention
    attn_mma<<<dim3(SEQ / 64, BH), 128, ATTN_SMEM>>>();

    // 3) output projection + bias
    gemm_mma<1, C><<<dim3(C / 128, MTOT / 256), 256, GEMM_SMEM>>>(go, wp, b_proj, out);
}

// round 7
// speedup vs baseline: 6.9536x; 1.8314x over previous
#include <cuda_runtime.h>
#include <cuda_fp16.h>
#include <cstdint>

// Problem constants
constexpr int B    = 2;
constexpr int SEQ  = 2048;
constexpr int C    = 1024;
constexpr int H    = 16;
constexpr int D    = 64;
constexpr int BH   = B * H;       // 32
constexpr int MTOT = B * SEQ;     // 4096
constexpr int KDIM = C;

// Scratch (allocation-free rule: __device__ globals), all fp16
__device__ __half g_q[BH * SEQ * D];    // pre-scaled by 1/8
__device__ __half g_k[BH * SEQ * D];
__device__ __half g_vt[BH * D * SEQ];   // V TRANSPOSED: [bh][d][seq]
__device__ __half g_o[MTOT * C];        // attention out
__device__ __half g_xh[MTOT * C];       // x -> fp16
__device__ __half g_wqkvh[3 * C * C];   // w_qkv -> fp16
__device__ __half g_wprojh[C * C];      // w_proj -> fp16

__device__ __forceinline__ unsigned packh2(float lo, float hi) {
    __half2 h = __floats2half2_rn(lo, hi);
    return *reinterpret_cast<unsigned*>(&h);
}

__device__ __forceinline__ void mma16(float* d, const unsigned* a, const unsigned* b) {
    asm volatile(
        "mma.sync.aligned.m16n8k16.row.col.f32.f16.f16.f32 "
        "{%0,%1,%2,%3}, {%4,%5,%6,%7}, {%8,%9}, {%0,%1,%2,%3};\n"
        : "+f"(d[0]), "+f"(d[1]), "+f"(d[2]), "+f"(d[3])
        : "r"(a[0]), "r"(a[1]), "r"(a[2]), "r"(a[3]), "r"(b[0]), "r"(b[1]));
}

__device__ __forceinline__ void ldmx4(unsigned& r0, unsigned& r1, unsigned& r2,
                                      unsigned& r3, uint32_t addr) {
    asm volatile("ldmatrix.sync.aligned.m8n8.x4.shared.b16 {%0,%1,%2,%3}, [%4];"
                 : "=r"(r0), "=r"(r1), "=r"(r2), "=r"(r3) : "r"(addr));
}

__device__ __forceinline__ void cpa16s(uint32_t dst, const void* src) {
    asm volatile("cp.async.cg.shared.global [%0], [%1], 16;\n" :: "r"(dst), "l"(src));
}
__device__ __forceinline__ void cpcommit() { asm volatile("cp.async.commit_group;\n"); }
template <int N> __device__ __forceinline__ void cpwait() {
    asm volatile("cp.async.wait_group %0;\n" :: "n"(N));
}

// ---------------------------------------------------------------------------
// Prepass: fp32 -> fp16 conversion (float4 granularity)
// ---------------------------------------------------------------------------
__global__ void to_half(const float* __restrict__ src, __half2* __restrict__ dst) {
    const int i = blockIdx.x * blockDim.x + threadIdx.x;
    float4 v = ((const float4*)src)[i];
    dst[2 * i + 0] = __floats2half2_rn(v.x, v.y);
    dst[2 * i + 1] = __floats2half2_rn(v.z, v.w);
}

// ---------------------------------------------------------------------------
// fp16 GEMM (NT): Y[m,j] = sum_k A[m,k]*W[j,k], fp32 accum.
// CTA 128x128x32(halves), 256 thr, 8 warps (2x4), warp tile 64x32.
// 3-stage cp.async; ldmatrix.x4 fragments; smem stride 40 halves (80B,
// conflict-free for both ldmatrix phases and cp.async stores).
// MODE 0: scatter -> g_q (x0.125), g_k, g_vt (transposed). MODE 1: bias+out.
// ---------------------------------------------------------------------------
template <int MODE, int NN>
__global__ __launch_bounds__(256, 1)
void gemm_h(const __half* __restrict__ A, const __half* __restrict__ W,
            const float* __restrict__ bias, float* __restrict__ out)
{
    constexpr int BM = 128, BK = 32, SA = BK + 8, STG = 3;   // SA=40 halves
    constexpr int ASZ = BM * SA;                              // 5120 halves/stage
    extern __shared__ __half smh[];
    const uint32_t smu = (uint32_t)__cvta_generic_to_shared(smh);

    const int tid  = threadIdx.x;
    const int warp = tid >> 5, lane = tid & 31;
    const int g = lane >> 2, t = lane & 3;
    const int wm = (warp >> 2) * 64;      // 0,64
    const int wn = (warp & 3) * 32;       // 0,32,64,96
    const int m0 = blockIdx.y * BM;
    const int n0 = blockIdx.x * BM;

    auto issue = [&](int kt, int buf) {
        const int k0 = kt * BK;
#pragma unroll
        for (int j = 0; j < 2; j++) {
            const int id = tid + j * 256;          // 0..511
            const int row = id >> 2, c8 = (id & 3) << 3;
            cpa16s(smu + 2u * (buf * ASZ + row * SA + c8),
                   A + (size_t)(m0 + row) * KDIM + k0 + c8);
            cpa16s(smu + 2u * (STG * ASZ + buf * ASZ + row * SA + c8),
                   W + (size_t)(n0 + row) * KDIM + k0 + c8);
        }
    };

    float acc[4][4][4];
#pragma unroll
    for (int mt = 0; mt < 4; mt++)
#pragma unroll
        for (int nt = 0; nt < 4; nt++)
#pragma unroll
            for (int j = 0; j < 4; j++) acc[mt][nt][j] = 0.f;

    constexpr int KT = KDIM / BK;  // 32
    issue(0, 0); cpcommit();
    issue(1, 1); cpcommit();

    // per-lane ldmatrix address offsets (halves)
    const int aRow = (lane & 15);
    const int aKof = (lane & 16) ? 8 : 0;
    const int bRow = ((lane >> 1) & 8) + (lane & 7);
    const int bKof = (lane & 8) ? 8 : 0;

    for (int kt = 0; kt < KT; ++kt) {
        cpwait<1>();
        __syncthreads();
        if (kt + 2 < KT) issue(kt + 2, (kt + 2) % STG);
        cpcommit();

        const uint32_t aBase = smu + 2u * ((kt % STG) * ASZ);
        const uint32_t bBase = smu + 2u * (STG * ASZ + (kt % STG) * ASZ);
#pragma unroll
        for (int ks = 0; ks < 2; ks++) {
            const int k0 = ks * 16;
            unsigned af[4][4], bf[4][2];
#pragma unroll
            for (int mt = 0; mt < 4; mt++)
                ldmx4(af[mt][0], af[mt][1], af[mt][2], af[mt][3],
                      aBase + 2u * ((wm + mt * 16 + aRow) * SA + k0 + aKof));
#pragma unroll
            for (int np = 0; np < 2; np++)
                ldmx4(bf[2 * np][0], bf[2 * np][1], bf[2 * np + 1][0], bf[2 * np + 1][1],
                      bBase + 2u * ((wn + np * 16 + bRow) * SA + k0 + bKof));
#pragma unroll
            for (int mt = 0; mt < 4; mt++)
#pragma unroll
                for (int nt = 0; nt < 4; nt++)
                    mma16(acc[mt][nt], af[mt], bf[nt]);
        }
    }

    // -------- epilogue --------
    if (MODE == 0) {
#pragma unroll
        for (int mt = 0; mt < 4; mt++) {
#pragma unroll
            for (int rr = 0; rr < 2; rr++) {
                const int m = m0 + wm + mt * 16 + g + rr * 8;
                const int bb = m >> 11;
                const int n = m & 2047;
#pragma unroll
                for (int nt = 0; nt < 4; nt++) {
                    const int col = n0 + wn + nt * 8 + 2 * t;
                    const float v0 = acc[mt][nt][rr * 2 + 0];
                    const float v1 = acc[mt][nt][rr * 2 + 1];
                    const int which = col >> 10;
                    const int r = col & 1023;
                    const int h = r >> 6;
                    const int d = r & 63;
                    if (which == 0) {
                        const size_t idx = ((size_t)((bb * H + h) * SEQ + n)) * D + d;
                        __half2 hv = __floats2half2_rn(v0 * 0.125f, v1 * 0.125f);
                        *reinterpret_cast<__half2*>(&g_q[idx]) = hv;
                    } else if (which == 1) {
                        const size_t idx = ((size_t)((bb * H + h) * SEQ + n)) * D + d;
                        *reinterpret_cast<__half2*>(&g_k[idx]) = __floats2half2_rn(v0, v1);
                    } else {
                        const size_t tb = ((size_t)(bb * H + h) * D + d) * SEQ + n;
                        g_vt[tb]       = __float2half_rn(v0);
                        g_vt[tb + SEQ] = __float2half_rn(v1);
                    }
                }
            }
        }
    } else {
#pragma unroll
        for (int mt = 0; mt < 4; mt++) {
#pragma unroll
            for (int rr = 0; rr < 2; rr++) {
                const int m = m0 + wm + mt * 16 + g + rr * 8;
#pragma unroll
                for (int nt = 0; nt < 4; nt++) {
                    const int col = n0 + wn + nt * 8 + 2 * t;
                    float2 v;
                    v.x = acc[mt][nt][rr * 2 + 0] + bias[col];
                    v.y = acc[mt][nt][rr * 2 + 1] + bias[col + 1];
                    *(float2*)(out + (size_t)m * NN + col) = v;
                }
            }
        }
    }
}

// ---------------------------------------------------------------------------
// Flash attention, fp16 MMA (m16n8k16), fp32 softmax/accum.
// CTA: 64 q-rows, 4 warps (16 each). KV tile 64, double-buffered cp.async.
// P stays in registers (fp16 A-frag == S accumulator layout). V pre-transposed.
// ---------------------------------------------------------------------------
__global__ __launch_bounds__(128)
void attn_h()
{
    constexpr int BKV = 64, SK = 72, SV = 72;           // halves
    constexpr int KSZ = BKV * SK, VSZ = BKV * SV;
    extern __shared__ __half smh[];
    const uint32_t smu = (uint32_t)__cvta_generic_to_shared(smh);
    const uint32_t vbase0 = smu + 2u * (2 * KSZ);

    const int tid = threadIdx.x, warp = tid >> 5, lane = tid & 31;
    const int g = lane >> 2, t = lane & 3;
    const int bh = blockIdx.y;
    const int q0 = blockIdx.x * 64 + warp * 16;

    const __half* Kb = g_k  + (size_t)bh * SEQ * D;
    const __half* Vb = g_vt + (size_t)bh * D * SEQ;

    auto issue_kv = [&](int tile, int buf) {
#pragma unroll
        for (int i = 0; i < 4; i++) {
            const int id = tid + i * 128;          // 0..511
            const int row = id >> 3, c8 = (id & 7) << 3;
            cpa16s(smu + 2u * (buf * KSZ + row * SK + c8),
                   Kb + (size_t)(tile * BKV + row) * D + c8);
            cpa16s(vbase0 + 2u * (buf * VSZ + row * SV + c8),
                   Vb + (size_t)row * SEQ + tile * BKV + c8);
        }
    };

    // Q fragments from gmem (pre-scaled fp16)
    unsigned qf[4][4];
    {
        const __half* Qb = g_q + ((size_t)bh * SEQ + q0) * D;
#pragma unroll
        for (int s = 0; s < 4; s++) {
            qf[s][0] = *(const unsigned*)(Qb + g * D + s * 16 + 2 * t);
            qf[s][1] = *(const unsigned*)(Qb + (g + 8) * D + s * 16 + 2 * t);
            qf[s][2] = *(const unsigned*)(Qb + g * D + s * 16 + 2 * t + 8);
            qf[s][3] = *(const unsigned*)(Qb + (g + 8) * D + s * 16 + 2 * t + 8);
        }
    }

    float o[8][4];
#pragma unroll
    for (int nt = 0; nt < 8; nt++)
#pragma unroll
        for (int j = 0; j < 4; j++) o[nt][j] = 0.f;
    float mr0 = -1e30f, mr1 = -1e30f, l0 = 0.f, l1 = 0.f;

    const int bRow = ((lane >> 1) & 8) + (lane & 7);
    const int bKof = (lane & 8) ? 8 : 0;

    constexpr int NT = SEQ / BKV;
    issue_kv(0, 0); cpcommit();

    for (int tile = 0; tile < NT; ++tile) {
        cpwait<0>();
        __syncthreads();
        if (tile + 1 < NT) issue_kv(tile + 1, (tile + 1) & 1);
        cpcommit();

        const uint32_t kb = smu + 2u * ((tile & 1) * KSZ);
        const uint32_t vb = vbase0 + 2u * ((tile & 1) * VSZ);

        // S = Q K^T (16 x 64 per warp)
        float s[8][4];
#pragma unroll
        for (int nt = 0; nt < 8; nt++)
#pragma unroll
            for (int j = 0; j < 4; j++) s[nt][j] = 0.f;
#pragma unroll
        for (int ks = 0; ks < 4; ks++) {
            unsigned bf[8][2];
#pragma unroll
            for (int np = 0; np < 4; np++)
                ldmx4(bf[2 * np][0], bf[2 * np][1], bf[2 * np + 1][0], bf[2 * np + 1][1],
                      kb + 2u * ((np * 16 + bRow) * SK + ks * 16 + bKof));
#pragma unroll
            for (int nt = 0; nt < 8; nt++) mma16(s[nt], qf[ks], bf[nt]);
        }

        // online softmax
        float mn0 = mr0, mn1 = mr1;
#pragma unroll
        for (int nt = 0; nt < 8; nt++) {
            mn0 = fmaxf(mn0, fmaxf(s[nt][0], s[nt][1]));
            mn1 = fmaxf(mn1, fmaxf(s[nt][2], s[nt][3]));
        }
        mn0 = fmaxf(mn0, __shfl_xor_sync(0xffffffffu, mn0, 1));
        mn0 = fmaxf(mn0, __shfl_xor_sync(0xffffffffu, mn0, 2));
        mn1 = fmaxf(mn1, __shfl_xor_sync(0xffffffffu, mn1, 1));
        mn1 = fmaxf(mn1, __shfl_xor_sync(0xffffffffu, mn1, 2));
        const float a0 = __expf(mr0 - mn0);
        const float a1 = __expf(mr1 - mn1);
        mr0 = mn0; mr1 = mn1;
        float ps0 = 0.f, ps1 = 0.f;
#pragma unroll
        for (int nt = 0; nt < 8; nt++) {
            s[nt][0] = __expf(s[nt][0] - mn0);
            s[nt][1] = __expf(s[nt][1] - mn0);
            s[nt][2] = __expf(s[nt][2] - mn1);
            s[nt][3] = __expf(s[nt][3] - mn1);
            ps0 += s[nt][0] + s[nt][1];
            ps1 += s[nt][2] + s[nt][3];
        }
        ps0 += __shfl_xor_sync(0xffffffffu, ps0, 1);
        ps0 += __shfl_xor_sync(0xffffffffu, ps0, 2);
        ps1 += __shfl_xor_sync(0xffffffffu, ps1, 1);
        ps1 += __shfl_xor_sync(0xffffffffu, ps1, 2);
        l0 = l0 * a0 + ps0;
        l1 = l1 * a1 + ps1;
#pragma unroll
        for (int nt = 0; nt < 8; nt++) {
            o[nt][0] *= a0; o[nt][1] *= a0;
            o[nt][2] *= a1; o[nt][3] *= a1;
        }

        // P -> fp16 A-fragments, entirely in registers
        unsigned pf[4][4];
#pragma unroll
        for (int s2 = 0; s2 < 4; s2++) {
            pf[s2][0] = packh2(s[2 * s2][0],     s[2 * s2][1]);
            pf[s2][1] = packh2(s[2 * s2][2],     s[2 * s2][3]);
            pf[s2][2] = packh2(s[2 * s2 + 1][0], s[2 * s2 + 1][1]);
            pf[s2][3] = packh2(s[2 * s2 + 1][2], s[2 * s2 + 1][3]);
        }

        // O += P V   (V transposed in smem: rows = d, cols = kv)
#pragma unroll
        for (int ks = 0; ks < 4; ks++) {
            unsigned bf[8][2];
#pragma unroll
            for (int np = 0; np < 4; np++)
                ldmx4(bf[2 * np][0], bf[2 * np][1], bf[2 * np + 1][0], bf[2 * np + 1][1],
                      vb + 2u * ((np * 16 + bRow) * SV + ks * 16 + bKof));
#pragma unroll
            for (int nt = 0; nt < 8; nt++) mma16(o[nt], pf[ks], bf[nt]);
        }
    }

    // normalize + write g_o (fp16) as [B,N,C]
    const float i0 = 1.f / l0, i1 = 1.f / l1;
    const int b = bh >> 4, h = bh & 15;
    __half* Ob = g_o + ((size_t)(b * SEQ) + q0) * C + h * D;
#pragma unroll
    for (int nt = 0; nt < 8; nt++) {
        *reinterpret_cast<__half2*>(&Ob[g * C + nt * 8 + 2 * t]) =
            __floats2half2_rn(o[nt][0] * i0, o[nt][1] * i0);
        *reinterpret_cast<__half2*>(&Ob[(g + 8) * C + nt * 8 + 2 * t]) =
            __floats2half2_rn(o[nt][2] * i1, o[nt][3] * i1);
    }
}

// ---------------------------------------------------------------------------
extern "C" void kernel_launch(void* const* d_in, const int* in_sizes, int n_in,
                              void* d_out, int out_size)
{
    const float* x      = (const float*)d_in[0];
    const float* w_qkv  = (const float*)d_in[1];
    const float* w_proj = (const float*)d_in[2];
    const float* b_proj = (const float*)d_in[3];
    float* out = (float*)d_out;

    constexpr int GEMM_SMEM = 3 * 2 * 128 * 40 * 2;           // 61440
    constexpr int ATTN_SMEM = 2 * 64 * (72 + 72) * 2;         // 36864
    cudaFuncSetAttribute(gemm_h<0, 3 * C>, cudaFuncAttributeMaxDynamicSharedMemorySize, GEMM_SMEM);
    cudaFuncSetAttribute(gemm_h<1, C>,     cudaFuncAttributeMaxDynamicSharedMemorySize, GEMM_SMEM);
    cudaFuncSetAttribute(attn_h,           cudaFuncAttributeMaxDynamicSharedMemorySize, ATTN_SMEM);

    __half *xh = nullptr, *wq = nullptr, *wp = nullptr, *go = nullptr;
    cudaGetSymbolAddress((void**)&xh, g_xh);
    cudaGetSymbolAddress((void**)&wq, g_wqkvh);
    cudaGetSymbolAddress((void**)&wp, g_wprojh);
    cudaGetSymbolAddress((void**)&go, g_o);

    // 0) fp32 -> fp16 inputs
    to_half<<<(MTOT * C / 4) / 256, 256>>>(x, (__half2*)xh);
    to_half<<<(3 * C * C / 4) / 256, 256>>>(w_qkv, (__half2*)wq);
    to_half<<<(C * C / 4) / 256, 256>>>(w_proj, (__half2*)wp);

    // 1) QKV projection -> g_q (scaled), g_k, g_vt (transposed)
    gemm_h<0, 3 * C><<<dim3(3 * C / 128, MTOT / 128), 256, GEMM_SMEM>>>(xh, wq, nullptr, nullptr);

    // 2) attention -> g_o
    attn_h<<<dim3(SEQ / 64, BH), 128, ATTN_SMEM>>>();

    // 3) output projection + bias -> out (fp32)
    gemm_h<1, C><<<dim3(C / 128, MTOT / 128), 256, GEMM_SMEM>>>(go, wp, b_proj, out);
}

// round 8
// speedup vs baseline: 7.9703x; 1.1462x over previous
#include <cuda_runtime.h>
#include <cuda_fp16.h>
#include <cstdint>

// Problem constants
constexpr int B    = 2;
constexpr int SEQ  = 2048;
constexpr int C    = 1024;
constexpr int H    = 16;
constexpr int D    = 64;
constexpr int BH   = B * H;       // 32
constexpr int MTOT = B * SEQ;     // 4096
constexpr int KDIM = C;

// Scratch (allocation-free rule: __device__ globals), all fp16
__device__ __half g_q[BH * SEQ * D];    // pre-scaled by 1/8
__device__ __half g_k[BH * SEQ * D];
__device__ __half g_vt[BH * D * SEQ];   // V TRANSPOSED: [bh][d][seq]
__device__ __half g_o[MTOT * C];        // attention out
__device__ __half g_xh[MTOT * C];       // x -> fp16
__device__ __half g_wqkvh[3 * C * C];   // w_qkv -> fp16
__device__ __half g_wprojh[C * C];      // w_proj -> fp16

__device__ __forceinline__ unsigned packh2(float lo, float hi) {
    __half2 h = __floats2half2_rn(lo, hi);
    return *reinterpret_cast<unsigned*>(&h);
}

__device__ __forceinline__ void mma16(float* d, const unsigned* a, const unsigned* b) {
    asm volatile(
        "mma.sync.aligned.m16n8k16.row.col.f32.f16.f16.f32 "
        "{%0,%1,%2,%3}, {%4,%5,%6,%7}, {%8,%9}, {%0,%1,%2,%3};\n"
        : "+f"(d[0]), "+f"(d[1]), "+f"(d[2]), "+f"(d[3])
        : "r"(a[0]), "r"(a[1]), "r"(a[2]), "r"(a[3]), "r"(b[0]), "r"(b[1]));
}

__device__ __forceinline__ void ldmx4(unsigned& r0, unsigned& r1, unsigned& r2,
                                      unsigned& r3, uint32_t addr) {
    asm volatile("ldmatrix.sync.aligned.m8n8.x4.shared.b16 {%0,%1,%2,%3}, [%4];"
                 : "=r"(r0), "=r"(r1), "=r"(r2), "=r"(r3) : "r"(addr));
}

__device__ __forceinline__ void cpa16s(uint32_t dst, const void* src) {
    asm volatile("cp.async.cg.shared.global [%0], [%1], 16;\n" :: "r"(dst), "l"(src));
}
__device__ __forceinline__ void cpcommit() { asm volatile("cp.async.commit_group;\n"); }
template <int N> __device__ __forceinline__ void cpwait() {
    asm volatile("cp.async.wait_group %0;\n" :: "n"(N));
}

// ---------------------------------------------------------------------------
// Prepass: fp32 -> fp16 conversion (float4 granularity)
// ---------------------------------------------------------------------------
__global__ void to_half(const float* __restrict__ src, __half2* __restrict__ dst) {
    const int i = blockIdx.x * blockDim.x + threadIdx.x;
    float4 v = ((const float4*)src)[i];
    dst[2 * i + 0] = __floats2half2_rn(v.x, v.y);
    dst[2 * i + 1] = __floats2half2_rn(v.z, v.w);
}

// ---------------------------------------------------------------------------
// fp16 GEMM (NT): Y[m,j] = sum_k A[m,k]*W[j,k], fp32 accum.
// CTA 128x128x32(halves), 256 thr, 8 warps (2x4), warp tile 64x32.
// 3-stage cp.async; ldmatrix.x4 fragments; smem stride 40 halves.
// __launch_bounds__(256,2): cap 128 regs -> 2 CTAs/SM (4 warps/SMSP).
// MODE 0: scatter -> g_q (x0.125), g_k, g_vt (transposed). MODE 1: bias+out.
// ---------------------------------------------------------------------------
template <int MODE, int NN>
__global__ __launch_bounds__(256, 2)
void gemm_h(const __half* __restrict__ A, const __half* __restrict__ W,
            const float* __restrict__ bias, float* __restrict__ out)
{
    constexpr int BM = 128, BK = 32, SA = BK + 8, STG = 3;   // SA=40 halves
    constexpr int ASZ = BM * SA;                              // 5120 halves/stage
    extern __shared__ __half smh[];
    const uint32_t smu = (uint32_t)__cvta_generic_to_shared(smh);

    const int tid  = threadIdx.x;
    const int warp = tid >> 5, lane = tid & 31;
    const int g = lane >> 2, t = lane & 3;
    const int wm = (warp >> 2) * 64;      // 0,64
    const int wn = (warp & 3) * 32;       // 0,32,64,96
    const int m0 = blockIdx.y * BM;
    const int n0 = blockIdx.x * BM;

    auto issue = [&](int kt, int buf) {
        const int k0 = kt * BK;
#pragma unroll
        for (int j = 0; j < 2; j++) {
            const int id = tid + j * 256;          // 0..511
            const int row = id >> 2, c8 = (id & 3) << 3;
            cpa16s(smu + 2u * (buf * ASZ + row * SA + c8),
                   A + (size_t)(m0 + row) * KDIM + k0 + c8);
            cpa16s(smu + 2u * (STG * ASZ + buf * ASZ + row * SA + c8),
                   W + (size_t)(n0 + row) * KDIM + k0 + c8);
        }
    };

    float acc[4][4][4];
#pragma unroll
    for (int mt = 0; mt < 4; mt++)
#pragma unroll
        for (int nt = 0; nt < 4; nt++)
#pragma unroll
            for (int j = 0; j < 4; j++) acc[mt][nt][j] = 0.f;

    constexpr int KT = KDIM / BK;  // 32
    issue(0, 0); cpcommit();
    issue(1, 1); cpcommit();

    // per-lane ldmatrix address offsets (halves)
    const int aRow = (lane & 15);
    const int aKof = (lane & 16) ? 8 : 0;
    const int bRow = ((lane >> 1) & 8) + (lane & 7);
    const int bKof = (lane & 8) ? 8 : 0;

    for (int kt = 0; kt < KT; ++kt) {
        cpwait<1>();
        __syncthreads();
        if (kt + 2 < KT) issue(kt + 2, (kt + 2) % STG);
        cpcommit();

        const uint32_t aBase = smu + 2u * ((kt % STG) * ASZ);
        const uint32_t bBase = smu + 2u * (STG * ASZ + (kt % STG) * ASZ);
#pragma unroll
        for (int ks = 0; ks < 2; ks++) {
            const int k0 = ks * 16;
            unsigned af[4][4], bf[4][2];
#pragma unroll
            for (int mt = 0; mt < 4; mt++)
                ldmx4(af[mt][0], af[mt][1], af[mt][2], af[mt][3],
                      aBase + 2u * ((wm + mt * 16 + aRow) * SA + k0 + aKof));
#pragma unroll
            for (int np = 0; np < 2; np++)
                ldmx4(bf[2 * np][0], bf[2 * np][1], bf[2 * np + 1][0], bf[2 * np + 1][1],
                      bBase + 2u * ((wn + np * 16 + bRow) * SA + k0 + bKof));
#pragma unroll
            for (int mt = 0; mt < 4; mt++)
#pragma unroll
                for (int nt = 0; nt < 4; nt++)
                    mma16(acc[mt][nt], af[mt], bf[nt]);
        }
    }

    // -------- epilogue --------
    if (MODE == 0) {
#pragma unroll
        for (int mt = 0; mt < 4; mt++) {
#pragma unroll
            for (int rr = 0; rr < 2; rr++) {
                const int m = m0 + wm + mt * 16 + g + rr * 8;
                const int bb = m >> 11;
                const int n = m & 2047;
#pragma unroll
                for (int nt = 0; nt < 4; nt++) {
                    const int col = n0 + wn + nt * 8 + 2 * t;
                    const float v0 = acc[mt][nt][rr * 2 + 0];
                    const float v1 = acc[mt][nt][rr * 2 + 1];
                    const int which = col >> 10;
                    const int r = col & 1023;
                    const int h = r >> 6;
                    const int d = r & 63;
                    if (which == 0) {
                        const size_t idx = ((size_t)((bb * H + h) * SEQ + n)) * D + d;
                        __half2 hv = __floats2half2_rn(v0 * 0.125f, v1 * 0.125f);
                        *reinterpret_cast<__half2*>(&g_q[idx]) = hv;
                    } else if (which == 1) {
                        const size_t idx = ((size_t)((bb * H + h) * SEQ + n)) * D + d;
                        *reinterpret_cast<__half2*>(&g_k[idx]) = __floats2half2_rn(v0, v1);
                    } else {
                        const size_t tb = ((size_t)(bb * H + h) * D + d) * SEQ + n;
                        g_vt[tb]       = __float2half_rn(v0);
                        g_vt[tb + SEQ] = __float2half_rn(v1);
                    }
                }
            }
        }
    } else {
#pragma unroll
        for (int mt = 0; mt < 4; mt++) {
#pragma unroll
            for (int rr = 0; rr < 2; rr++) {
                const int m = m0 + wm + mt * 16 + g + rr * 8;
#pragma unroll
                for (int nt = 0; nt < 4; nt++) {
                    const int col = n0 + wn + nt * 8 + 2 * t;
                    float2 v;
                    v.x = acc[mt][nt][rr * 2 + 0] + bias[col];
                    v.y = acc[mt][nt][rr * 2 + 1] + bias[col + 1];
                    *(float2*)(out + (size_t)m * NN + col) = v;
                }
            }
        }
    }
}

// ---------------------------------------------------------------------------
// Flash attention, fp16 MMA (m16n8k16), fp32 softmax/accum.
// CTA: 64 q-rows, 4 warps (16 each). KV tile 64, double-buffered cp.async.
// P stays in registers. V pre-transposed. (128,4): cap 128 regs, 4 CTAs/SM.
// ---------------------------------------------------------------------------
__global__ __launch_bounds__(128, 4)
void attn_h()
{
    constexpr int BKV = 64, SK = 72, SV = 72;           // halves
    constexpr int KSZ = BKV * SK, VSZ = BKV * SV;
    extern __shared__ __half smh[];
    const uint32_t smu = (uint32_t)__cvta_generic_to_shared(smh);
    const uint32_t vbase0 = smu + 2u * (2 * KSZ);

    const int tid = threadIdx.x, warp = tid >> 5, lane = tid & 31;
    const int g = lane >> 2, t = lane & 3;
    const int bh = blockIdx.y;
    const int q0 = blockIdx.x * 64 + warp * 16;

    const __half* Kb = g_k  + (size_t)bh * SEQ * D;
    const __half* Vb = g_vt + (size_t)bh * D * SEQ;

    auto issue_kv = [&](int tile, int buf) {
#pragma unroll
        for (int i = 0; i < 4; i++) {
            const int id = tid + i * 128;          // 0..511
            const int row = id >> 3, c8 = (id & 7) << 3;
            cpa16s(smu + 2u * (buf * KSZ + row * SK + c8),
                   Kb + (size_t)(tile * BKV + row) * D + c8);
            cpa16s(vbase0 + 2u * (buf * VSZ + row * SV + c8),
                   Vb + (size_t)row * SEQ + tile * BKV + c8);
        }
    };

    // Q fragments from gmem (pre-scaled fp16)
    unsigned qf[4][4];
    {
        const __half* Qb = g_q + ((size_t)bh * SEQ + q0) * D;
#pragma unroll
        for (int s = 0; s < 4; s++) {
            qf[s][0] = *(const unsigned*)(Qb + g * D + s * 16 + 2 * t);
            qf[s][1] = *(const unsigned*)(Qb + (g + 8) * D + s * 16 + 2 * t);
            qf[s][2] = *(const unsigned*)(Qb + g * D + s * 16 + 2 * t + 8);
            qf[s][3] = *(const unsigned*)(Qb + (g + 8) * D + s * 16 + 2 * t + 8);
        }
    }

    float o[8][4];
#pragma unroll
    for (int nt = 0; nt < 8; nt++)
#pragma unroll
        for (int j = 0; j < 4; j++) o[nt][j] = 0.f;
    float mr0 = -1e30f, mr1 = -1e30f, l0 = 0.f, l1 = 0.f;

    const int bRow = ((lane >> 1) & 8) + (lane & 7);
    const int bKof = (lane & 8) ? 8 : 0;

    constexpr int NT = SEQ / BKV;
    issue_kv(0, 0); cpcommit();

    for (int tile = 0; tile < NT; ++tile) {
        cpwait<0>();
        __syncthreads();
        if (tile + 1 < NT) issue_kv(tile + 1, (tile + 1) & 1);
        cpcommit();

        const uint32_t kb = smu + 2u * ((tile & 1) * KSZ);
        const uint32_t vb = vbase0 + 2u * ((tile & 1) * VSZ);

        // S = Q K^T (16 x 64 per warp)
        float s[8][4];
#pragma unroll
        for (int nt = 0; nt < 8; nt++)
#pragma unroll
            for (int j = 0; j < 4; j++) s[nt][j] = 0.f;
#pragma unroll
        for (int ks = 0; ks < 4; ks++) {
            unsigned bf[8][2];
#pragma unroll
            for (int np = 0; np < 4; np++)
                ldmx4(bf[2 * np][0], bf[2 * np][1], bf[2 * np + 1][0], bf[2 * np + 1][1],
                      kb + 2u * ((np * 16 + bRow) * SK + ks * 16 + bKof));
#pragma unroll
            for (int nt = 0; nt < 8; nt++) mma16(s[nt], qf[ks], bf[nt]);
        }

        // online softmax
        float mn0 = mr0, mn1 = mr1;
#pragma unroll
        for (int nt = 0; nt < 8; nt++) {
            mn0 = fmaxf(mn0, fmaxf(s[nt][0], s[nt][1]));
            mn1 = fmaxf(mn1, fmaxf(s[nt][2], s[nt][3]));
        }
        mn0 = fmaxf(mn0, __shfl_xor_sync(0xffffffffu, mn0, 1));
        mn0 = fmaxf(mn0, __shfl_xor_sync(0xffffffffu, mn0, 2));
        mn1 = fmaxf(mn1, __shfl_xor_sync(0xffffffffu, mn1, 1));
        mn1 = fmaxf(mn1, __shfl_xor_sync(0xffffffffu, mn1, 2));
        const float a0 = __expf(mr0 - mn0);
        const float a1 = __expf(mr1 - mn1);
        mr0 = mn0; mr1 = mn1;
        float ps0 = 0.f, ps1 = 0.f;
#pragma unroll
        for (int nt = 0; nt < 8; nt++) {
            s[nt][0] = __expf(s[nt][0] - mn0);
            s[nt][1] = __expf(s[nt][1] - mn0);
            s[nt][2] = __expf(s[nt][2] - mn1);
            s[nt][3] = __expf(s[nt][3] - mn1);
            ps0 += s[nt][0] + s[nt][1];
            ps1 += s[nt][2] + s[nt][3];
        }
        ps0 += __shfl_xor_sync(0xffffffffu, ps0, 1);
        ps0 += __shfl_xor_sync(0xffffffffu, ps0, 2);
        ps1 += __shfl_xor_sync(0xffffffffu, ps1, 1);
        ps1 += __shfl_xor_sync(0xffffffffu, ps1, 2);
        l0 = l0 * a0 + ps0;
        l1 = l1 * a1 + ps1;
#pragma unroll
        for (int nt = 0; nt < 8; nt++) {
            o[nt][0] *= a0; o[nt][1] *= a0;
            o[nt][2] *= a1; o[nt][3] *= a1;
        }

        // P -> fp16 A-fragments, entirely in registers
        unsigned pf[4][4];
#pragma unroll
        for (int s2 = 0; s2 < 4; s2++) {
            pf[s2][0] = packh2(s[2 * s2][0],     s[2 * s2][1]);
            pf[s2][1] = packh2(s[2 * s2][2],     s[2 * s2][3]);
            pf[s2][2] = packh2(s[2 * s2 + 1][0], s[2 * s2 + 1][1]);
            pf[s2][3] = packh2(s[2 * s2 + 1][2], s[2 * s2 + 1][3]);
        }

        // O += P V   (V transposed in smem: rows = d, cols = kv)
#pragma unroll
        for (int ks = 0; ks < 4; ks++) {
            unsigned bf[8][2];
#pragma unroll
            for (int np = 0; np < 4; np++)
                ldmx4(bf[2 * np][0], bf[2 * np][1], bf[2 * np + 1][0], bf[2 * np + 1][1],
                      vb + 2u * ((np * 16 + bRow) * SV + ks * 16 + bKof));
#pragma unroll
            for (int nt = 0; nt < 8; nt++) mma16(o[nt], pf[ks], bf[nt]);
        }
    }

    // normalize + write g_o (fp16) as [B,N,C]
    const float i0 = 1.f / l0, i1 = 1.f / l1;
    const int b = bh >> 4, h = bh & 15;
    __half* Ob = g_o + ((size_t)(b * SEQ) + q0) * C + h * D;
#pragma unroll
    for (int nt = 0; nt < 8; nt++) {
        *reinterpret_cast<__half2*>(&Ob[g * C + nt * 8 + 2 * t]) =
            __floats2half2_rn(o[nt][0] * i0, o[nt][1] * i0);
        *reinterpret_cast<__half2*>(&Ob[(g + 8) * C + nt * 8 + 2 * t]) =
            __floats2half2_rn(o[nt][2] * i1, o[nt][3] * i1);
    }
}

// ---------------------------------------------------------------------------
extern "C" void kernel_launch(void* const* d_in, const int* in_sizes, int n_in,
                              void* d_out, int out_size)
{
    const float* x      = (const float*)d_in[0];
    const float* w_qkv  = (const float*)d_in[1];
    const float* w_proj = (const float*)d_in[2];
    const float* b_proj = (const float*)d_in[3];
    float* out = (float*)d_out;

    constexpr int GEMM_SMEM = 3 * 2 * 128 * 40 * 2;           // 61440
    constexpr int ATTN_SMEM = 2 * 64 * (72 + 72) * 2;         // 36864
    cudaFuncSetAttribute(gemm_h<0, 3 * C>, cudaFuncAttributeMaxDynamicSharedMemorySize, GEMM_SMEM);
    cudaFuncSetAttribute(gemm_h<1, C>,     cudaFuncAttributeMaxDynamicSharedMemorySize, GEMM_SMEM);
    cudaFuncSetAttribute(attn_h,           cudaFuncAttributeMaxDynamicSharedMemorySize, ATTN_SMEM);

    __half *xh = nullptr, *wq = nullptr, *wp = nullptr, *go = nullptr;
    cudaGetSymbolAddress((void**)&xh, g_xh);
    cudaGetSymbolAddress((void**)&wq, g_wqkvh);
    cudaGetSymbolAddress((void**)&wp, g_wprojh);
    cudaGetSymbolAddress((void**)&go, g_o);

    // 0) fp32 -> fp16 inputs
    to_half<<<(MTOT * C / 4) / 256, 256>>>(x, (__half2*)xh);
    to_half<<<(3 * C * C / 4) / 256, 256>>>(w_qkv, (__half2*)wq);
    to_half<<<(C * C / 4) / 256, 256>>>(w_proj, (__half2*)wp);

    // 1) QKV projection -> g_q (scaled), g_k, g_vt (transposed)
    gemm_h<0, 3 * C><<<dim3(3 * C / 128, MTOT / 128), 256, GEMM_SMEM>>>(xh, wq, nullptr, nullptr);

    // 2) attention -> g_o
    attn_h<<<dim3(SEQ / 64, BH), 128, ATTN_SMEM>>>();

    // 3) output projection + bias -> out (fp32)
    gemm_h<1, C><<<dim3(C / 128, MTOT / 128), 256, GEMM_SMEM>>>(go, wp, b_proj, out);
}

// round 9
// speedup vs baseline: 8.4452x; 1.0596x over previous
#include <cuda_runtime.h>
#include <cuda_fp16.h>
#include <cstdint>

// Problem constants
constexpr int B    = 2;
constexpr int SEQ  = 2048;
constexpr int C    = 1024;
constexpr int H    = 16;
constexpr int D    = 64;
constexpr int BH   = B * H;       // 32
constexpr int MTOT = B * SEQ;     // 4096
constexpr int KDIM = C;

// Scratch (allocation-free rule: __device__ globals), all fp16
__device__ __half g_q[BH * SEQ * D];    // pre-scaled by 1/8
__device__ __half g_k[BH * SEQ * D];
__device__ __half g_vt[BH * D * SEQ];   // V TRANSPOSED: [bh][d][seq]
__device__ __half g_o[MTOT * C];        // attention out
__device__ __half g_xh[MTOT * C];       // x -> fp16
__device__ __half g_wqkvh[3 * C * C];   // w_qkv -> fp16
__device__ __half g_wprojh[C * C];      // w_proj -> fp16

__device__ __forceinline__ unsigned packh2(float lo, float hi) {
    __half2 h = __floats2half2_rn(lo, hi);
    return *reinterpret_cast<unsigned*>(&h);
}

__device__ __forceinline__ void mma16(float* d, const unsigned* a, const unsigned* b) {
    asm volatile(
        "mma.sync.aligned.m16n8k16.row.col.f32.f16.f16.f32 "
        "{%0,%1,%2,%3}, {%4,%5,%6,%7}, {%8,%9}, {%0,%1,%2,%3};\n"
        : "+f"(d[0]), "+f"(d[1]), "+f"(d[2]), "+f"(d[3])
        : "r"(a[0]), "r"(a[1]), "r"(a[2]), "r"(a[3]), "r"(b[0]), "r"(b[1]));
}

__device__ __forceinline__ void ldmx4(unsigned& r0, unsigned& r1, unsigned& r2,
                                      unsigned& r3, uint32_t addr) {
    asm volatile("ldmatrix.sync.aligned.m8n8.x4.shared.b16 {%0,%1,%2,%3}, [%4];"
                 : "=r"(r0), "=r"(r1), "=r"(r2), "=r"(r3) : "r"(addr));
}

__device__ __forceinline__ void cpa16s(uint32_t dst, const void* src) {
    asm volatile("cp.async.cg.shared.global [%0], [%1], 16;\n" :: "r"(dst), "l"(src));
}
__device__ __forceinline__ void cpcommit() { asm volatile("cp.async.commit_group;\n"); }
template <int N> __device__ __forceinline__ void cpwait() {
    asm volatile("cp.async.wait_group %0;\n" :: "n"(N));
}

// ---------------------------------------------------------------------------
// Fused prepass: fp32 -> fp16 for x, w_qkv, w_proj in one launch.
// ---------------------------------------------------------------------------
constexpr int NX = MTOT * C / 4;       // 1048576 float4s
constexpr int NQ = 3 * C * C / 4;      // 786432
constexpr int NP = C * C / 4;          // 262144

__global__ void to_half_all(const float* __restrict__ x,
                            const float* __restrict__ wq,
                            const float* __restrict__ wp) {
    const int i = blockIdx.x * blockDim.x + threadIdx.x;
    const float* src;
    __half2* dst;
    int j;
    if (i < NX)            { src = x;  dst = (__half2*)g_xh;    j = i; }
    else if (i < NX + NQ)  { src = wq; dst = (__half2*)g_wqkvh; j = i - NX; }
    else                   { src = wp; dst = (__half2*)g_wprojh; j = i - NX - NQ; }
    float4 v = ((const float4*)src)[j];
    dst[2 * j + 0] = __floats2half2_rn(v.x, v.y);
    dst[2 * j + 1] = __floats2half2_rn(v.z, v.w);
}

// ---------------------------------------------------------------------------
// fp16 GEMM (NT): Y[m,j] = sum_k A[m,k]*W[j,k], fp32 accum.
// CTA 128x128x64(halves), 256 thr, 8 warps (2x4), warp tile 64x32.
// 3-stage cp.async (110.6 KB smem, 2 CTAs/SM); 16 barriers total;
// 64 MMAs/warp between barriers; ldmatrix.x4 fragments, SA=72 conflict-free.
// MODE 0: scatter -> g_q (x0.125), g_k, g_vt (transposed). MODE 1: bias+out.
// ---------------------------------------------------------------------------
template <int MODE, int NN>
__global__ __launch_bounds__(256, 2)
void gemm_h(const __half* __restrict__ A, const __half* __restrict__ W,
            const float* __restrict__ bias, float* __restrict__ out)
{
    constexpr int BM = 128, BK = 64, SA = BK + 8, STG = 3;   // SA=72 halves
    constexpr int ASZ = BM * SA;                              // 9216 halves/stage
    extern __shared__ __half smh[];
    const uint32_t smu = (uint32_t)__cvta_generic_to_shared(smh);

    const int tid  = threadIdx.x;
    const int warp = tid >> 5, lane = tid & 31;
    const int g = lane >> 2, t = lane & 3;
    const int wm = (warp >> 2) * 64;      // 0,64
    const int wn = (warp & 3) * 32;       // 0,32,64,96
    const int m0 = blockIdx.y * BM;
    const int n0 = blockIdx.x * BM;

    auto issue = [&](int kt, int buf) {
        const int k0 = kt * BK;
#pragma unroll
        for (int j = 0; j < 4; j++) {
            const int id = tid + j * 256;          // 0..1023
            const int row = id >> 3, c8 = (id & 7) << 3;
            cpa16s(smu + 2u * (buf * ASZ + row * SA + c8),
                   A + (size_t)(m0 + row) * KDIM + k0 + c8);
            cpa16s(smu + 2u * (STG * ASZ + buf * ASZ + row * SA + c8),
                   W + (size_t)(n0 + row) * KDIM + k0 + c8);
        }
    };

    float acc[4][4][4];
#pragma unroll
    for (int mt = 0; mt < 4; mt++)
#pragma unroll
        for (int nt = 0; nt < 4; nt++)
#pragma unroll
            for (int j = 0; j < 4; j++) acc[mt][nt][j] = 0.f;

    constexpr int KT = KDIM / BK;  // 16
    issue(0, 0); cpcommit();
    issue(1, 1); cpcommit();

    // per-lane ldmatrix address offsets (halves)
    const int aRow = (lane & 15);
    const int aKof = (lane & 16) ? 8 : 0;
    const int bRow = ((lane >> 1) & 8) + (lane & 7);
    const int bKof = (lane & 8) ? 8 : 0;

    for (int kt = 0; kt < KT; ++kt) {
        cpwait<1>();
        __syncthreads();
        if (kt + 2 < KT) issue(kt + 2, (kt + 2) % STG);
        cpcommit();

        const uint32_t aBase = smu + 2u * ((kt % STG) * ASZ);
        const uint32_t bBase = smu + 2u * (STG * ASZ + (kt % STG) * ASZ);
#pragma unroll
        for (int ks = 0; ks < 4; ks++) {
            const int k0 = ks * 16;
            unsigned af[4][4], bf[4][2];
#pragma unroll
            for (int mt = 0; mt < 4; mt++)
                ldmx4(af[mt][0], af[mt][1], af[mt][2], af[mt][3],
                      aBase + 2u * ((wm + mt * 16 + aRow) * SA + k0 + aKof));
#pragma unroll
            for (int np = 0; np < 2; np++)
                ldmx4(bf[2 * np][0], bf[2 * np][1], bf[2 * np + 1][0], bf[2 * np + 1][1],
                      bBase + 2u * ((wn + np * 16 + bRow) * SA + k0 + bKof));
#pragma unroll
            for (int mt = 0; mt < 4; mt++)
#pragma unroll
                for (int nt = 0; nt < 4; nt++)
                    mma16(acc[mt][nt], af[mt], bf[nt]);
        }
    }

    // -------- epilogue --------
    if (MODE == 0) {
#pragma unroll
        for (int mt = 0; mt < 4; mt++) {
#pragma unroll
            for (int rr = 0; rr < 2; rr++) {
                const int m = m0 + wm + mt * 16 + g + rr * 8;
                const int bb = m >> 11;
                const int n = m & 2047;
#pragma unroll
                for (int nt = 0; nt < 4; nt++) {
                    const int col = n0 + wn + nt * 8 + 2 * t;
                    const float v0 = acc[mt][nt][rr * 2 + 0];
                    const float v1 = acc[mt][nt][rr * 2 + 1];
                    const int which = col >> 10;
                    const int r = col & 1023;
                    const int h = r >> 6;
                    const int d = r & 63;
                    if (which == 0) {
                        const size_t idx = ((size_t)((bb * H + h) * SEQ + n)) * D + d;
                        __half2 hv = __floats2half2_rn(v0 * 0.125f, v1 * 0.125f);
                        *reinterpret_cast<__half2*>(&g_q[idx]) = hv;
                    } else if (which == 1) {
                        const size_t idx = ((size_t)((bb * H + h) * SEQ + n)) * D + d;
                        *reinterpret_cast<__half2*>(&g_k[idx]) = __floats2half2_rn(v0, v1);
                    } else {
                        const size_t tb = ((size_t)(bb * H + h) * D + d) * SEQ + n;
                        g_vt[tb]       = __float2half_rn(v0);
                        g_vt[tb + SEQ] = __float2half_rn(v1);
                    }
                }
            }
        }
    } else {
#pragma unroll
        for (int mt = 0; mt < 4; mt++) {
#pragma unroll
            for (int rr = 0; rr < 2; rr++) {
                const int m = m0 + wm + mt * 16 + g + rr * 8;
#pragma unroll
                for (int nt = 0; nt < 4; nt++) {
                    const int col = n0 + wn + nt * 8 + 2 * t;
                    float2 v;
                    v.x = acc[mt][nt][rr * 2 + 0] + bias[col];
                    v.y = acc[mt][nt][rr * 2 + 1] + bias[col + 1];
                    *(float2*)(out + (size_t)m * NN + col) = v;
                }
            }
        }
    }
}

// ---------------------------------------------------------------------------
// Flash attention, fp16 MMA (m16n8k16), fp32 softmax/accum.
// CTA: 64 q-rows, 4 warps (16 each). KV tile 64, double-buffered cp.async.
// P stays in registers. V pre-transposed. (128,4): cap 128 regs, 4 CTAs/SM.
// (Unchanged — measured at ~90% of HMMA roofline.)
// ---------------------------------------------------------------------------
__global__ __launch_bounds__(128, 4)
void attn_h()
{
    constexpr int BKV = 64, SK = 72, SV = 72;           // halves
    constexpr int KSZ = BKV * SK, VSZ = BKV * SV;
    extern __shared__ __half smh[];
    const uint32_t smu = (uint32_t)__cvta_generic_to_shared(smh);
    const uint32_t vbase0 = smu + 2u * (2 * KSZ);

    const int tid = threadIdx.x, warp = tid >> 5, lane = tid & 31;
    const int g = lane >> 2, t = lane & 3;
    const int bh = blockIdx.y;
    const int q0 = blockIdx.x * 64 + warp * 16;

    const __half* Kb = g_k  + (size_t)bh * SEQ * D;
    const __half* Vb = g_vt + (size_t)bh * D * SEQ;

    auto issue_kv = [&](int tile, int buf) {
#pragma unroll
        for (int i = 0; i < 4; i++) {
            const int id = tid + i * 128;          // 0..511
            const int row = id >> 3, c8 = (id & 7) << 3;
            cpa16s(smu + 2u * (buf * KSZ + row * SK + c8),
                   Kb + (size_t)(tile * BKV + row) * D + c8);
            cpa16s(vbase0 + 2u * (buf * VSZ + row * SV + c8),
                   Vb + (size_t)row * SEQ + tile * BKV + c8);
        }
    };

    // Q fragments from gmem (pre-scaled fp16)
    unsigned qf[4][4];
    {
        const __half* Qb = g_q + ((size_t)bh * SEQ + q0) * D;
#pragma unroll
        for (int s = 0; s < 4; s++) {
            qf[s][0] = *(const unsigned*)(Qb + g * D + s * 16 + 2 * t);
            qf[s][1] = *(const unsigned*)(Qb + (g + 8) * D + s * 16 + 2 * t);
            qf[s][2] = *(const unsigned*)(Qb + g * D + s * 16 + 2 * t + 8);
            qf[s][3] = *(const unsigned*)(Qb + (g + 8) * D + s * 16 + 2 * t + 8);
        }
    }

    float o[8][4];
#pragma unroll
    for (int nt = 0; nt < 8; nt++)
#pragma unroll
        for (int j = 0; j < 4; j++) o[nt][j] = 0.f;
    float mr0 = -1e30f, mr1 = -1e30f, l0 = 0.f, l1 = 0.f;

    const int bRow = ((lane >> 1) & 8) + (lane & 7);
    const int bKof = (lane & 8) ? 8 : 0;

    constexpr int NT = SEQ / BKV;
    issue_kv(0, 0); cpcommit();

    for (int tile = 0; tile < NT; ++tile) {
        cpwait<0>();
        __syncthreads();
        if (tile + 1 < NT) issue_kv(tile + 1, (tile + 1) & 1);
        cpcommit();

        const uint32_t kb = smu + 2u * ((tile & 1) * KSZ);
        const uint32_t vb = vbase0 + 2u * ((tile & 1) * VSZ);

        // S = Q K^T (16 x 64 per warp)
        float s[8][4];
#pragma unroll
        for (int nt = 0; nt < 8; nt++)
#pragma unroll
            for (int j = 0; j < 4; j++) s[nt][j] = 0.f;
#pragma unroll
        for (int ks = 0; ks < 4; ks++) {
            unsigned bf[8][2];
#pragma unroll
            for (int np = 0; np < 4; np++)
                ldmx4(bf[2 * np][0], bf[2 * np][1], bf[2 * np + 1][0], bf[2 * np + 1][1],
                      kb + 2u * ((np * 16 + bRow) * SK + ks * 16 + bKof));
#pragma unroll
            for (int nt = 0; nt < 8; nt++) mma16(s[nt], qf[ks], bf[nt]);
        }

        // online softmax
        float mn0 = mr0, mn1 = mr1;
#pragma unroll
        for (int nt = 0; nt < 8; nt++) {
            mn0 = fmaxf(mn0, fmaxf(s[nt][0], s[nt][1]));
            mn1 = fmaxf(mn1, fmaxf(s[nt][2], s[nt][3]));
        }
        mn0 = fmaxf(mn0, __shfl_xor_sync(0xffffffffu, mn0, 1));
        mn0 = fmaxf(mn0, __shfl_xor_sync(0xffffffffu, mn0, 2));
        mn1 = fmaxf(mn1, __shfl_xor_sync(0xffffffffu, mn1, 1));
        mn1 = fmaxf(mn1, __shfl_xor_sync(0xffffffffu, mn1, 2));
        const float a0 = __expf(mr0 - mn0);
        const float a1 = __expf(mr1 - mn1);
        mr0 = mn0; mr1 = mn1;
        float ps0 = 0.f, ps1 = 0.f;
#pragma unroll
        for (int nt = 0; nt < 8; nt++) {
            s[nt][0] = __expf(s[nt][0] - mn0);
            s[nt][1] = __expf(s[nt][1] - mn0);
            s[nt][2] = __expf(s[nt][2] - mn1);
            s[nt][3] = __expf(s[nt][3] - mn1);
            ps0 += s[nt][0] + s[nt][1];
            ps1 += s[nt][2] + s[nt][3];
        }
        ps0 += __shfl_xor_sync(0xffffffffu, ps0, 1);
        ps0 += __shfl_xor_sync(0xffffffffu, ps0, 2);
        ps1 += __shfl_xor_sync(0xffffffffu, ps1, 1);
        ps1 += __shfl_xor_sync(0xffffffffu, ps1, 2);
        l0 = l0 * a0 + ps0;
        l1 = l1 * a1 + ps1;
#pragma unroll
        for (int nt = 0; nt < 8; nt++) {
            o[nt][0] *= a0; o[nt][1] *= a0;
            o[nt][2] *= a1; o[nt][3] *= a1;
        }

        // P -> fp16 A-fragments, entirely in registers
        unsigned pf[4][4];
#pragma unroll
        for (int s2 = 0; s2 < 4; s2++) {
            pf[s2][0] = packh2(s[2 * s2][0],     s[2 * s2][1]);
            pf[s2][1] = packh2(s[2 * s2][2],     s[2 * s2][3]);
            pf[s2][2] = packh2(s[2 * s2 + 1][0], s[2 * s2 + 1][1]);
            pf[s2][3] = packh2(s[2 * s2 + 1][2], s[2 * s2 + 1][3]);
        }

        // O += P V   (V transposed in smem: rows = d, cols = kv)
#pragma unroll
        for (int ks = 0; ks < 4; ks++) {
            unsigned bf[8][2];
#pragma unroll
            for (int np = 0; np < 4; np++)
                ldmx4(bf[2 * np][0], bf[2 * np][1], bf[2 * np + 1][0], bf[2 * np + 1][1],
                      vb + 2u * ((np * 16 + bRow) * SV + ks * 16 + bKof));
#pragma unroll
            for (int nt = 0; nt < 8; nt++) mma16(o[nt], pf[ks], bf[nt]);
        }
    }

    // normalize + write g_o (fp16) as [B,N,C]
    const float i0 = 1.f / l0, i1 = 1.f / l1;
    const int b = bh >> 4, h = bh & 15;
    __half* Ob = g_o + ((size_t)(b * SEQ) + q0) * C + h * D;
#pragma unroll
    for (int nt = 0; nt < 8; nt++) {
        *reinterpret_cast<__half2*>(&Ob[g * C + nt * 8 + 2 * t]) =
            __floats2half2_rn(o[nt][0] * i0, o[nt][1] * i0);
        *reinterpret_cast<__half2*>(&Ob[(g + 8) * C + nt * 8 + 2 * t]) =
            __floats2half2_rn(o[nt][2] * i1, o[nt][3] * i1);
    }
}

// ---------------------------------------------------------------------------
extern "C" void kernel_launch(void* const* d_in, const int* in_sizes, int n_in,
                              void* d_out, int out_size)
{
    const float* x      = (const float*)d_in[0];
    const float* w_qkv  = (const float*)d_in[1];
    const float* w_proj = (const float*)d_in[2];
    const float* b_proj = (const float*)d_in[3];
    float* out = (float*)d_out;

    constexpr int GEMM_SMEM = 3 * 2 * 128 * 72 * 2;           // 110592
    constexpr int ATTN_SMEM = 2 * 64 * (72 + 72) * 2;         // 36864
    cudaFuncSetAttribute(gemm_h<0, 3 * C>, cudaFuncAttributeMaxDynamicSharedMemorySize, GEMM_SMEM);
    cudaFuncSetAttribute(gemm_h<1, C>,     cudaFuncAttributeMaxDynamicSharedMemorySize, GEMM_SMEM);
    cudaFuncSetAttribute(attn_h,           cudaFuncAttributeMaxDynamicSharedMemorySize, ATTN_SMEM);

    __half *xh = nullptr, *wq = nullptr, *wp = nullptr, *go = nullptr;
    cudaGetSymbolAddress((void**)&xh, g_xh);
    cudaGetSymbolAddress((void**)&wq, g_wqkvh);
    cudaGetSymbolAddress((void**)&wp, g_wprojh);
    cudaGetSymbolAddress((void**)&go, g_o);

    // 0) fp32 -> fp16 inputs (single fused launch)
    to_half_all<<<(NX + NQ + NP) / 256, 256>>>(x, w_qkv, w_proj);

    // 1) QKV projection -> g_q (scaled), g_k, g_vt (transposed)
    gemm_h<0, 3 * C><<<dim3(3 * C / 128, MTOT / 128), 256, GEMM_SMEM>>>(xh, wq, nullptr, nullptr);

    // 2) attention -> g_o
    attn_h<<<dim3(SEQ / 64, BH), 128, ATTN_SMEM>>>();

    // 3) output projection + bias -> out (fp32)
    gemm_h<1, C><<<dim3(C / 128, MTOT / 128), 256, GEMM_SMEM>>>(go, wp, b_proj, out);
}

// round 10
// speedup vs baseline: 8.4787x; 1.0040x over previous
#include <cuda_runtime.h>
#include <cuda_fp16.h>
#include <cstdint>

// Problem constants
constexpr int B    = 2;
constexpr int SEQ  = 2048;
constexpr int C    = 1024;
constexpr int H    = 16;
constexpr int D    = 64;
constexpr int BH   = B * H;       // 32
constexpr int MTOT = B * SEQ;     // 4096
constexpr int KDIM = C;

// Scratch (allocation-free rule: __device__ globals), all fp16
__device__ __half g_q[BH * SEQ * D];    // pre-scaled by 1/8
__device__ __half g_k[BH * SEQ * D];
__device__ __half g_vt[BH * D * SEQ];   // V TRANSPOSED: [bh][d][seq]
__device__ __half g_o[MTOT * C];        // attention out
__device__ __half g_xh[MTOT * C];       // x -> fp16
__device__ __half g_wqkvh[3 * C * C];   // w_qkv -> fp16
__device__ __half g_wprojh[C * C];      // w_proj -> fp16

__device__ __forceinline__ unsigned packh2(float lo, float hi) {
    __half2 h = __floats2half2_rn(lo, hi);
    return *reinterpret_cast<unsigned*>(&h);
}

__device__ __forceinline__ void mma16(float* d, const unsigned* a, const unsigned* b) {
    asm volatile(
        "mma.sync.aligned.m16n8k16.row.col.f32.f16.f16.f32 "
        "{%0,%1,%2,%3}, {%4,%5,%6,%7}, {%8,%9}, {%0,%1,%2,%3};\n"
        : "+f"(d[0]), "+f"(d[1]), "+f"(d[2]), "+f"(d[3])
        : "r"(a[0]), "r"(a[1]), "r"(a[2]), "r"(a[3]), "r"(b[0]), "r"(b[1]));
}

// fp16-accumulate variant (2 output regs = 4 halves)
__device__ __forceinline__ void mma16h(unsigned* d, const unsigned* a, const unsigned* b) {
    asm volatile(
        "mma.sync.aligned.m16n8k16.row.col.f16.f16.f16.f16 "
        "{%0,%1}, {%2,%3,%4,%5}, {%6,%7}, {%0,%1};\n"
        : "+r"(d[0]), "+r"(d[1])
        : "r"(a[0]), "r"(a[1]), "r"(a[2]), "r"(a[3]), "r"(b[0]), "r"(b[1]));
}

__device__ __forceinline__ void ldmx4(unsigned& r0, unsigned& r1, unsigned& r2,
                                      unsigned& r3, uint32_t addr) {
    asm volatile("ldmatrix.sync.aligned.m8n8.x4.shared.b16 {%0,%1,%2,%3}, [%4];"
                 : "=r"(r0), "=r"(r1), "=r"(r2), "=r"(r3) : "r"(addr));
}

__device__ __forceinline__ void cpa16s(uint32_t dst, const void* src) {
    asm volatile("cp.async.cg.shared.global [%0], [%1], 16;\n" :: "r"(dst), "l"(src));
}
__device__ __forceinline__ void cpcommit() { asm volatile("cp.async.commit_group;\n"); }
template <int N> __device__ __forceinline__ void cpwait() {
    asm volatile("cp.async.wait_group %0;\n" :: "n"(N));
}

// ---------------------------------------------------------------------------
// Fused prepass: fp32 -> fp16 for x, w_qkv, w_proj in one launch.
// ---------------------------------------------------------------------------
constexpr int NX = MTOT * C / 4;       // 1048576 float4s
constexpr int NQ = 3 * C * C / 4;      // 786432
constexpr int NP = C * C / 4;          // 262144

__global__ void to_half_all(const float* __restrict__ x,
                            const float* __restrict__ wq,
                            const float* __restrict__ wp) {
    const int i = blockIdx.x * blockDim.x + threadIdx.x;
    const float* src;
    __half2* dst;
    int j;
    if (i < NX)            { src = x;  dst = (__half2*)g_xh;    j = i; }
    else if (i < NX + NQ)  { src = wq; dst = (__half2*)g_wqkvh; j = i - NX; }
    else                   { src = wp; dst = (__half2*)g_wprojh; j = i - NX - NQ; }
    float4 v = ((const float4*)src)[j];
    dst[2 * j + 0] = __floats2half2_rn(v.x, v.y);
    dst[2 * j + 1] = __floats2half2_rn(v.z, v.w);
}

// ---------------------------------------------------------------------------
// fp16 GEMM (NT): Y[m,j] = sum_k A[m,k]*W[j,k], fp32 accum.  (unchanged)
// CTA 128x128x64(halves), 256 thr, 8 warps (2x4), warp tile 64x32.
// ---------------------------------------------------------------------------
template <int MODE, int NN>
__global__ __launch_bounds__(256, 2)
void gemm_h(const __half* __restrict__ A, const __half* __restrict__ W,
            const float* __restrict__ bias, float* __restrict__ out)
{
    constexpr int BM = 128, BK = 64, SA = BK + 8, STG = 3;   // SA=72 halves
    constexpr int ASZ = BM * SA;                              // 9216 halves/stage
    extern __shared__ __half smh[];
    const uint32_t smu = (uint32_t)__cvta_generic_to_shared(smh);

    const int tid  = threadIdx.x;
    const int warp = tid >> 5, lane = tid & 31;
    const int g = lane >> 2, t = lane & 3;
    const int wm = (warp >> 2) * 64;      // 0,64
    const int wn = (warp & 3) * 32;       // 0,32,64,96
    const int m0 = blockIdx.y * BM;
    const int n0 = blockIdx.x * BM;

    auto issue = [&](int kt, int buf) {
        const int k0 = kt * BK;
#pragma unroll
        for (int j = 0; j < 4; j++) {
            const int id = tid + j * 256;          // 0..1023
            const int row = id >> 3, c8 = (id & 7) << 3;
            cpa16s(smu + 2u * (buf * ASZ + row * SA + c8),
                   A + (size_t)(m0 + row) * KDIM + k0 + c8);
            cpa16s(smu + 2u * (STG * ASZ + buf * ASZ + row * SA + c8),
                   W + (size_t)(n0 + row) * KDIM + k0 + c8);
        }
    };

    float acc[4][4][4];
#pragma unroll
    for (int mt = 0; mt < 4; mt++)
#pragma unroll
        for (int nt = 0; nt < 4; nt++)
#pragma unroll
            for (int j = 0; j < 4; j++) acc[mt][nt][j] = 0.f;

    constexpr int KT = KDIM / BK;  // 16
    issue(0, 0); cpcommit();
    issue(1, 1); cpcommit();

    const int aRow = (lane & 15);
    const int aKof = (lane & 16) ? 8 : 0;
    const int bRow = ((lane >> 1) & 8) + (lane & 7);
    const int bKof = (lane & 8) ? 8 : 0;

    for (int kt = 0; kt < KT; ++kt) {
        cpwait<1>();
        __syncthreads();
        if (kt + 2 < KT) issue(kt + 2, (kt + 2) % STG);
        cpcommit();

        const uint32_t aBase = smu + 2u * ((kt % STG) * ASZ);
        const uint32_t bBase = smu + 2u * (STG * ASZ + (kt % STG) * ASZ);
#pragma unroll
        for (int ks = 0; ks < 4; ks++) {
            const int k0 = ks * 16;
            unsigned af[4][4], bf[4][2];
#pragma unroll
            for (int mt = 0; mt < 4; mt++)
                ldmx4(af[mt][0], af[mt][1], af[mt][2], af[mt][3],
                      aBase + 2u * ((wm + mt * 16 + aRow) * SA + k0 + aKof));
#pragma unroll
            for (int np = 0; np < 2; np++)
                ldmx4(bf[2 * np][0], bf[2 * np][1], bf[2 * np + 1][0], bf[2 * np + 1][1],
                      bBase + 2u * ((wn + np * 16 + bRow) * SA + k0 + bKof));
#pragma unroll
            for (int mt = 0; mt < 4; mt++)
#pragma unroll
                for (int nt = 0; nt < 4; nt++)
                    mma16(acc[mt][nt], af[mt], bf[nt]);
        }
    }

    // -------- epilogue --------
    if (MODE == 0) {
#pragma unroll
        for (int mt = 0; mt < 4; mt++) {
#pragma unroll
            for (int rr = 0; rr < 2; rr++) {
                const int m = m0 + wm + mt * 16 + g + rr * 8;
                const int bb = m >> 11;
                const int n = m & 2047;
#pragma unroll
                for (int nt = 0; nt < 4; nt++) {
                    const int col = n0 + wn + nt * 8 + 2 * t;
                    const float v0 = acc[mt][nt][rr * 2 + 0];
                    const float v1 = acc[mt][nt][rr * 2 + 1];
                    const int which = col >> 10;
                    const int r = col & 1023;
                    const int h = r >> 6;
                    const int d = r & 63;
                    if (which == 0) {
                        const size_t idx = ((size_t)((bb * H + h) * SEQ + n)) * D + d;
                        __half2 hv = __floats2half2_rn(v0 * 0.125f, v1 * 0.125f);
                        *reinterpret_cast<__half2*>(&g_q[idx]) = hv;
                    } else if (which == 1) {
                        const size_t idx = ((size_t)((bb * H + h) * SEQ + n)) * D + d;
                        *reinterpret_cast<__half2*>(&g_k[idx]) = __floats2half2_rn(v0, v1);
                    } else {
                        const size_t tb = ((size_t)(bb * H + h) * D + d) * SEQ + n;
                        g_vt[tb]       = __float2half_rn(v0);
                        g_vt[tb + SEQ] = __float2half_rn(v1);
                    }
                }
            }
        }
    } else {
#pragma unroll
        for (int mt = 0; mt < 4; mt++) {
#pragma unroll
            for (int rr = 0; rr < 2; rr++) {
                const int m = m0 + wm + mt * 16 + g + rr * 8;
#pragma unroll
                for (int nt = 0; nt < 4; nt++) {
                    const int col = n0 + wn + nt * 8 + 2 * t;
                    float2 v;
                    v.x = acc[mt][nt][rr * 2 + 0] + bias[col];
                    v.y = acc[mt][nt][rr * 2 + 1] + bias[col + 1];
                    *(float2*)(out + (size_t)m * NN + col) = v;
                }
            }
        }
    }
}

// ---------------------------------------------------------------------------
// Flash attention. QK^T now uses fp16-ACCUMULATE MMA (error impact through
// softmax is ~1e-5; tests whether legacy f16-acc HMMA is double-rate).
// PV stays f32-accumulate. Everything else unchanged.
// ---------------------------------------------------------------------------
__global__ __launch_bounds__(128, 4)
void attn_h()
{
    constexpr int BKV = 64, SK = 72, SV = 72;           // halves
    constexpr int KSZ = BKV * SK, VSZ = BKV * SV;
    extern __shared__ __half smh[];
    const uint32_t smu = (uint32_t)__cvta_generic_to_shared(smh);
    const uint32_t vbase0 = smu + 2u * (2 * KSZ);

    const int tid = threadIdx.x, warp = tid >> 5, lane = tid & 31;
    const int g = lane >> 2, t = lane & 3;
    const int bh = blockIdx.y;
    const int q0 = blockIdx.x * 64 + warp * 16;

    const __half* Kb = g_k  + (size_t)bh * SEQ * D;
    const __half* Vb = g_vt + (size_t)bh * D * SEQ;

    auto issue_kv = [&](int tile, int buf) {
#pragma unroll
        for (int i = 0; i < 4; i++) {
            const int id = tid + i * 128;          // 0..511
            const int row = id >> 3, c8 = (id & 7) << 3;
            cpa16s(smu + 2u * (buf * KSZ + row * SK + c8),
                   Kb + (size_t)(tile * BKV + row) * D + c8);
            cpa16s(vbase0 + 2u * (buf * VSZ + row * SV + c8),
                   Vb + (size_t)row * SEQ + tile * BKV + c8);
        }
    };

    // Q fragments from gmem (pre-scaled fp16)
    unsigned qf[4][4];
    {
        const __half* Qb = g_q + ((size_t)bh * SEQ + q0) * D;
#pragma unroll
        for (int s = 0; s < 4; s++) {
            qf[s][0] = *(const unsigned*)(Qb + g * D + s * 16 + 2 * t);
            qf[s][1] = *(const unsigned*)(Qb + (g + 8) * D + s * 16 + 2 * t);
            qf[s][2] = *(const unsigned*)(Qb + g * D + s * 16 + 2 * t + 8);
            qf[s][3] = *(const unsigned*)(Qb + (g + 8) * D + s * 16 + 2 * t + 8);
        }
    }

    float o[8][4];
#pragma unroll
    for (int nt = 0; nt < 8; nt++)
#pragma unroll
        for (int j = 0; j < 4; j++) o[nt][j] = 0.f;
    float mr0 = -1e30f, mr1 = -1e30f, l0 = 0.f, l1 = 0.f;

    const int bRow = ((lane >> 1) & 8) + (lane & 7);
    const int bKof = (lane & 8) ? 8 : 0;

    constexpr int NT = SEQ / BKV;
    issue_kv(0, 0); cpcommit();

    for (int tile = 0; tile < NT; ++tile) {
        cpwait<0>();
        __syncthreads();
        if (tile + 1 < NT) issue_kv(tile + 1, (tile + 1) & 1);
        cpcommit();

        const uint32_t kb = smu + 2u * ((tile & 1) * KSZ);
        const uint32_t vb = vbase0 + 2u * ((tile & 1) * VSZ);

        // S = Q K^T (16 x 64 per warp), fp16 accumulate
        unsigned sh[8][2];
#pragma unroll
        for (int nt = 0; nt < 8; nt++) { sh[nt][0] = 0u; sh[nt][1] = 0u; }
#pragma unroll
        for (int ks = 0; ks < 4; ks++) {
            unsigned bf[8][2];
#pragma unroll
            for (int np = 0; np < 4; np++)
                ldmx4(bf[2 * np][0], bf[2 * np][1], bf[2 * np + 1][0], bf[2 * np + 1][1],
                      kb + 2u * ((np * 16 + bRow) * SK + ks * 16 + bKof));
#pragma unroll
            for (int nt = 0; nt < 8; nt++) mma16h(sh[nt], qf[ks], bf[nt]);
        }

        // unpack S to fp32 for softmax
        float s[8][4];
#pragma unroll
        for (int nt = 0; nt < 8; nt++) {
            float2 f0 = __half22float2(*reinterpret_cast<__half2*>(&sh[nt][0]));
            float2 f1 = __half22float2(*reinterpret_cast<__half2*>(&sh[nt][1]));
            s[nt][0] = f0.x; s[nt][1] = f0.y;
            s[nt][2] = f1.x; s[nt][3] = f1.y;
        }

        // online softmax
        float mn0 = mr0, mn1 = mr1;
#pragma unroll
        for (int nt = 0; nt < 8; nt++) {
            mn0 = fmaxf(mn0, fmaxf(s[nt][0], s[nt][1]));
            mn1 = fmaxf(mn1, fmaxf(s[nt][2], s[nt][3]));
        }
        mn0 = fmaxf(mn0, __shfl_xor_sync(0xffffffffu, mn0, 1));
        mn0 = fmaxf(mn0, __shfl_xor_sync(0xffffffffu, mn0, 2));
        mn1 = fmaxf(mn1, __shfl_xor_sync(0xffffffffu, mn1, 1));
        mn1 = fmaxf(mn1, __shfl_xor_sync(0xffffffffu, mn1, 2));
        const float a0 = __expf(mr0 - mn0);
        const float a1 = __expf(mr1 - mn1);
        mr0 = mn0; mr1 = mn1;
        float ps0 = 0.f, ps1 = 0.f;
#pragma unroll
        for (int nt = 0; nt < 8; nt++) {
            s[nt][0] = __expf(s[nt][0] - mn0);
            s[nt][1] = __expf(s[nt][1] - mn0);
            s[nt][2] = __expf(s[nt][2] - mn1);
            s[nt][3] = __expf(s[nt][3] - mn1);
            ps0 += s[nt][0] + s[nt][1];
            ps1 += s[nt][2] + s[nt][3];
        }
        ps0 += __shfl_xor_sync(0xffffffffu, ps0, 1);
        ps0 += __shfl_xor_sync(0xffffffffu, ps0, 2);
        ps1 += __shfl_xor_sync(0xffffffffu, ps1, 1);
        ps1 += __shfl_xor_sync(0xffffffffu, ps1, 2);
        l0 = l0 * a0 + ps0;
        l1 = l1 * a1 + ps1;
#pragma unroll
        for (int nt = 0; nt < 8; nt++) {
            o[nt][0] *= a0; o[nt][1] *= a0;
            o[nt][2] *= a1; o[nt][3] *= a1;
        }

        // P -> fp16 A-fragments, entirely in registers
        unsigned pf[4][4];
#pragma unroll
        for (int s2 = 0; s2 < 4; s2++) {
            pf[s2][0] = packh2(s[2 * s2][0],     s[2 * s2][1]);
            pf[s2][1] = packh2(s[2 * s2][2],     s[2 * s2][3]);
            pf[s2][2] = packh2(s[2 * s2 + 1][0], s[2 * s2 + 1][1]);
            pf[s2][3] = packh2(s[2 * s2 + 1][2], s[2 * s2 + 1][3]);
        }

        // O += P V   (V transposed in smem: rows = d, cols = kv), f32 accum
#pragma unroll
        for (int ks = 0; ks < 4; ks++) {
            unsigned bf[8][2];
#pragma unroll
            for (int np = 0; np < 4; np++)
                ldmx4(bf[2 * np][0], bf[2 * np][1], bf[2 * np + 1][0], bf[2 * np + 1][1],
                      vb + 2u * ((np * 16 + bRow) * SV + ks * 16 + bKof));
#pragma unroll
            for (int nt = 0; nt < 8; nt++) mma16(o[nt], pf[ks], bf[nt]);
        }
    }

    // normalize + write g_o (fp16) as [B,N,C]
    const float i0 = 1.f / l0, i1 = 1.f / l1;
    const int b = bh >> 4, h = bh & 15;
    __half* Ob = g_o + ((size_t)(b * SEQ) + q0) * C + h * D;
#pragma unroll
    for (int nt = 0; nt < 8; nt++) {
        *reinterpret_cast<__half2*>(&Ob[g * C + nt * 8 + 2 * t]) =
            __floats2half2_rn(o[nt][0] * i0, o[nt][1] * i0);
        *reinterpret_cast<__half2*>(&Ob[(g + 8) * C + nt * 8 + 2 * t]) =
            __floats2half2_rn(o[nt][2] * i1, o[nt][3] * i1);
    }
}

// ---------------------------------------------------------------------------
extern "C" void kernel_launch(void* const* d_in, const int* in_sizes, int n_in,
                              void* d_out, int out_size)
{
    const float* x      = (const float*)d_in[0];
    const float* w_qkv  = (const float*)d_in[1];
    const float* w_proj = (const float*)d_in[2];
    const float* b_proj = (const float*)d_in[3];
    float* out = (float*)d_out;

    constexpr int GEMM_SMEM = 3 * 2 * 128 * 72 * 2;           // 110592
    constexpr int ATTN_SMEM = 2 * 64 * (72 + 72) * 2;         // 36864
    cudaFuncSetAttribute(gemm_h<0, 3 * C>, cudaFuncAttributeMaxDynamicSharedMemorySize, GEMM_SMEM);
    cudaFuncSetAttribute(gemm_h<1, C>,     cudaFuncAttributeMaxDynamicSharedMemorySize, GEMM_SMEM);
    cudaFuncSetAttribute(attn_h,           cudaFuncAttributeMaxDynamicSharedMemorySize, ATTN_SMEM);

    __half *xh = nullptr, *wq = nullptr, *wp = nullptr, *go = nullptr;
    cudaGetSymbolAddress((void**)&xh, g_xh);
    cudaGetSymbolAddress((void**)&wq, g_wqkvh);
    cudaGetSymbolAddress((void**)&wp, g_wprojh);
    cudaGetSymbolAddress((void**)&go, g_o);

    // 0) fp32 -> fp16 inputs (single fused launch)
    to_half_all<<<(NX + NQ + NP) / 256, 256>>>(x, w_qkv, w_proj);

    // 1) QKV projection -> g_q (scaled), g_k, g_vt (transposed)
    gemm_h<0, 3 * C><<<dim3(3 * C / 128, MTOT / 128), 256, GEMM_SMEM>>>(xh, wq, nullptr, nullptr);

    // 2) attention -> g_o
    attn_h<<<dim3(SEQ / 64, BH), 128, ATTN_SMEM>>>();

    // 3) output projection + bias -> out (fp32)
    gemm_h<1, C><<<dim3(C / 128, MTOT / 128), 256, GEMM_SMEM>>>(go, wp, b_proj, out);
}